// round 13
// baseline (speedup 1.0000x reference)
#include <cuda_runtime.h>
#include <cuda_bf16.h>
#include <math.h>
#include <stdint.h>

#define BB 2
#define SS 2048
#define DD 1024
#define HH 16
#define DH 64
#define NROW (BB*SS)
#define OUT_ELEMS ((size_t)BB*SS*DD)

// Scratch (device globals)
__device__ __nv_bfloat16 g_Ah[NROW*DD];
__device__ __nv_bfloat16 g_Al[NROW*DD];
__device__ __nv_bfloat16 g_Sqh[NROW*DD], g_Sql[NROW*DD];
__device__ __nv_bfloat16 g_Skh[NROW*DD], g_Skl[NROW*DD];
__device__ __nv_bfloat16 g_Svh[NROW*DD], g_Svl[NROW*DD];
__device__ __nv_bfloat16 g_W1h[DD*DD], g_W1l[DD*DD];
__device__ __nv_bfloat16 g_W2h[DD*DD], g_W2l[DD*DD];
__device__ __nv_bfloat16 g_W3h[DD*DD], g_W3l[DD*DD];
__device__ __nv_bfloat16 g_W4h[DD*DD], g_W4l[DD*DD];
__device__ __nv_bfloat16 g_Qh[NROW*DD], g_Ql[NROW*DD];
__device__ __nv_bfloat16 g_Kh[NROW*DD], g_Kl[NROW*DD];
__device__ __nv_bfloat16 g_Vh[NROW*DD], g_Vl[NROW*DD];

// ===========================================================================
// helpers
// ===========================================================================
__device__ __forceinline__ float fast_exp2(float x) {
    float r;
    asm("ex2.approx.f32 %0, %1;" : "=f"(r) : "f"(x));
    return r;
}
__device__ __forceinline__ uint32_t smem_u32(const void* p) {
    uint32_t a;
    asm("{ .reg .u64 t; cvta.to.shared.u64 t, %1; cvt.u32.u64 %0, t; }"
        : "=r"(a) : "l"(p));
    return a;
}
__device__ __forceinline__ uint32_t sw128(uint32_t off) {
    return off ^ ((off >> 3) & 0x70);
}
__device__ __forceinline__ void cp16(uint32_t dst, const void* src) {
    asm volatile("cp.async.cg.shared.global [%0], [%1], 16;"
                 :: "r"(dst), "l"(src));
}
__device__ __forceinline__ void cp_commit() {
    asm volatile("cp.async.commit_group;" ::: "memory");
}
__device__ __forceinline__ void ldsm_x4(uint32_t& r0, uint32_t& r1,
                                        uint32_t& r2, uint32_t& r3, uint32_t a) {
    asm volatile("ldmatrix.sync.aligned.m8n8.x4.shared.b16 {%0,%1,%2,%3}, [%4];"
                 : "=r"(r0), "=r"(r1), "=r"(r2), "=r"(r3) : "r"(a));
}
__device__ __forceinline__ void ldsm_x4t(uint32_t& r0, uint32_t& r1,
                                         uint32_t& r2, uint32_t& r3, uint32_t a) {
    asm volatile("ldmatrix.sync.aligned.m8n8.x4.trans.shared.b16 {%0,%1,%2,%3}, [%4];"
                 : "=r"(r0), "=r"(r1), "=r"(r2), "=r"(r3) : "r"(a));
}
__device__ __forceinline__ void mma16816(float* d, const uint32_t* a, const uint32_t* b) {
    asm volatile(
        "mma.sync.aligned.m16n8k16.row.col.f32.bf16.bf16.f32 "
        "{%0,%1,%2,%3}, {%4,%5,%6,%7}, {%8,%9}, {%0,%1,%2,%3};"
        : "+f"(d[0]), "+f"(d[1]), "+f"(d[2]), "+f"(d[3])
        : "r"(a[0]), "r"(a[1]), "r"(a[2]), "r"(a[3]), "r"(b[0]), "r"(b[1]));
}
__device__ __forceinline__ uint32_t pack_bf16x2(float lo, float hi) {
    uint32_t r;
    asm("cvt.rn.bf16x2.f32 %0, %1, %2;" : "=r"(r) : "f"(hi), "f"(lo));
    return r;
}

// ===========================================================================
// batched fp32 -> bf16 hi/lo split
// ===========================================================================
struct SplitJob { const float4* in; uint2* hi; uint2* lo; int n4; };
struct SplitJobs { SplitJob j[7]; };

__device__ __forceinline__ void do_split(const float4* in, uint2* hi, uint2* lo, int i) {
    float4 v = in[i];
    float f[4] = {v.x, v.y, v.z, v.w};
    uint16_t h[4], l[4];
    #pragma unroll
    for (int j = 0; j < 4; j++) {
        __nv_bfloat16 hb = __float2bfloat16(f[j]);
        __nv_bfloat16 lb = __float2bfloat16(f[j] - __bfloat162float(hb));
        h[j] = __bfloat16_as_ushort(hb);
        l[j] = __bfloat16_as_ushort(lb);
    }
    hi[i] = make_uint2((uint32_t)h[0] | ((uint32_t)h[1] << 16),
                       (uint32_t)h[2] | ((uint32_t)h[3] << 16));
    lo[i] = make_uint2((uint32_t)l[0] | ((uint32_t)l[1] << 16),
                       (uint32_t)l[2] | ((uint32_t)l[3] << 16));
}

__global__ __launch_bounds__(256) void split_batch(SplitJobs jobs) {
    SplitJob jb = jobs.j[blockIdx.y];
    int i = blockIdx.x * 256 + threadIdx.x;
    if (i >= jb.n4) return;
    do_split(jb.in, jb.hi, jb.lo, i);
}

// ===========================================================================
// HMMA bf16-split GEMM core — 512 threads, 16 warps (4M x 4N), warp 32x32
// ===========================================================================
#define NTS 16
#define GSTAGE 65536
#define SM_GEMM_BYTES 131072

struct GemmJob {
    const __nv_bfloat16 *ah, *al, *wh, *wl;
    const float* bias;
    __nv_bfloat16 *ch, *cl;
    float scale;
};
struct GemmJobs { GemmJob j[3]; };

__device__ __forceinline__ void gemm_core(
    const __nv_bfloat16* __restrict__ Agh, const __nv_bfloat16* __restrict__ Agl,
    const __nv_bfloat16* __restrict__ Wgh, const __nv_bfloat16* __restrict__ Wgl,
    const float* __restrict__ bias, float* __restrict__ C,
    __nv_bfloat16* __restrict__ Ch, __nv_bfloat16* __restrict__ Cl,
    float scale, int mode, char* smc)
{
    const uint32_t sb = smem_u32(smc);
    const int t = threadIdx.x;
    const int lane = t & 31;
    const int wid = t >> 5;        // 0..15
    const int wm = wid & 3;        // 4 warps over M (32 rows each)
    const int wn = wid >> 2;       // 4 warps over N (32 cols each)
    const int m0 = blockIdx.y * 128;
    const int n0 = blockIdx.x * 128;

    float acc[2][4][4] = {};

    auto prefetch = [&](int s) {
        const int ksl = s * 64;
        const uint32_t base = sb + (s & 1) * GSTAGE;
        #pragma unroll
        for (int i = 0; i < 2; i++) {
            int idx = t + i * 512;
            int row = idx >> 3, ck = idx & 7;
            uint32_t so = sw128((uint32_t)(row * 128 + ck * 16));
            size_t g = (size_t)(m0 + row) * DD + ksl + ck * 8;
            cp16(base + so, Agh + g);
            cp16(base + 16384 + so, Agl + g);
        }
        #pragma unroll
        for (int i = 0; i < 2; i++) {
            int idx = t + i * 512;
            int kr = idx >> 4, cn = idx & 15;
            uint32_t so = (uint32_t)((cn >> 3) * 8192)
                        + sw128((uint32_t)(kr * 128 + (cn & 7) * 16));
            size_t g = (size_t)(ksl + kr) * DD + n0 + cn * 8;
            cp16(base + 32768 + so, Wgh + g);
            cp16(base + 49152 + so, Wgl + g);
        }
        cp_commit();
    };

    prefetch(0);
    prefetch(1);

    for (int s = 0; s < NTS; s++) {
        if (s < NTS - 1) asm volatile("cp.async.wait_group 1;" ::: "memory");
        else             asm volatile("cp.async.wait_group 0;" ::: "memory");
        __syncthreads();

        const uint32_t aB  = sb + (s & 1) * GSTAGE;
        const uint32_t alB = aB + 16384;
        const uint32_t bhB = aB + 32768;
        const uint32_t blB = aB + 49152;

        const int lg = lane >> 3, l7 = lane & 7;

        #pragma unroll
        for (int ks = 0; ks < 4; ks++) {
            const int kb = ks * 32;
            uint32_t bh[4][2], bl[4][2];
            #pragma unroll
            for (int jj = 0; jj < 2; jj++) {
                int nloc = wn * 32 + jj * 16;
                uint32_t stb = (uint32_t)((nloc >> 6) * 8192);
                int ncol = nloc & 63;
                int krow = ks * 16 + (lg & 1) * 8 + l7;
                uint32_t off = stb + sw128((uint32_t)(krow * 128 + ncol * 2 + (lg >> 1) * 16));
                uint32_t r0, r1, r2, r3;
                ldsm_x4t(r0, r1, r2, r3, bhB + off);
                bh[jj*2+0][0] = r0; bh[jj*2+0][1] = r1;
                bh[jj*2+1][0] = r2; bh[jj*2+1][1] = r3;
                ldsm_x4t(r0, r1, r2, r3, blB + off);
                bl[jj*2+0][0] = r0; bl[jj*2+0][1] = r1;
                bl[jj*2+1][0] = r2; bl[jj*2+1][1] = r3;
            }
            #pragma unroll
            for (int im = 0; im < 2; im++) {
                int arow = wm * 32 + im * 16 + (lg & 1) * 8 + l7;
                uint32_t off = sw128((uint32_t)(arow * 128 + kb + (lg >> 1) * 16));
                uint32_t ah[4], al[4];
                ldsm_x4(ah[0], ah[1], ah[2], ah[3], aB + off);
                ldsm_x4(al[0], al[1], al[2], al[3], alB + off);
                #pragma unroll
                for (int jn = 0; jn < 4; jn++) mma16816(acc[im][jn], ah, bh[jn]);
                #pragma unroll
                for (int jn = 0; jn < 4; jn++) mma16816(acc[im][jn], ah, bl[jn]);
                #pragma unroll
                for (int jn = 0; jn < 4; jn++) mma16816(acc[im][jn], al, bh[jn]);
            }
        }
        __syncthreads();
        if (s + 2 < NTS) prefetch(s + 2);
    }

    #pragma unroll
    for (int im = 0; im < 2; im++) {
        int r0 = m0 + wm * 32 + im * 16 + (lane >> 2);
        #pragma unroll
        for (int jn = 0; jn < 4; jn++) {
            int col = n0 + wn * 32 + jn * 8 + (lane & 3) * 2;
            float b0 = bias[col], b1 = bias[col + 1];
            float v00 = acc[im][jn][0] + b0, v01 = acc[im][jn][1] + b1;
            float v10 = acc[im][jn][2] + b0, v11 = acc[im][jn][3] + b1;
            if (mode == 0) {
                *(float2*)&C[(size_t)r0 * DD + col] = make_float2(v00, v01);
                *(float2*)&C[(size_t)(r0 + 8) * DD + col] = make_float2(v10, v11);
            } else {
                v00 *= scale; v01 *= scale; v10 *= scale; v11 *= scale;
                int h = col >> 6, dd = col & 63;
                int b_ = r0 >> 11, s0 = r0 & 2047;
                int b2 = (r0 + 8) >> 11, s1 = (r0 + 8) & 2047;
                size_t off0 = ((size_t)(b_ * HH + h) * SS + s0) * DH + dd;
                size_t off1 = ((size_t)(b2 * HH + h) * SS + s1) * DH + dd;
                uint32_t p0 = pack_bf16x2(v00, v01);
                uint32_t p1 = pack_bf16x2(v10, v11);
                *(uint32_t*)&Ch[off0] = p0;
                *(uint32_t*)&Ch[off1] = p1;
                uint32_t q0 = pack_bf16x2(v00 - __uint_as_float(p0 << 16),
                                          v01 - __uint_as_float(p0 & 0xffff0000u));
                uint32_t q1 = pack_bf16x2(v10 - __uint_as_float(p1 << 16),
                                          v11 - __uint_as_float(p1 & 0xffff0000u));
                *(uint32_t*)&Cl[off0] = q0;
                *(uint32_t*)&Cl[off1] = q1;
            }
        }
    }
}

__global__ __launch_bounds__(512, 1) void gemm_hmma_qkv(GemmJobs jobs) {
    extern __shared__ char smc[];
    GemmJob jb = jobs.j[blockIdx.z];
    gemm_core(jb.ah, jb.al, jb.wh, jb.wl, jb.bias, nullptr,
              jb.ch, jb.cl, jb.scale, 2, smc);
}

__global__ __launch_bounds__(512, 1) void gemm_hmma_out(
    const __nv_bfloat16* __restrict__ Agh, const __nv_bfloat16* __restrict__ Agl,
    const __nv_bfloat16* __restrict__ Wgh, const __nv_bfloat16* __restrict__ Wgl,
    const float* __restrict__ bias, float* __restrict__ C)
{
    extern __shared__ char smc[];
    gemm_core(Agh, Agl, Wgh, Wgl, bias, C, nullptr, nullptr, 1.0f, 0, smc);
}

// ===========================================================================
// Fused attention (R12 best: HMMA, 4Mx2C warp tiling) — UNCHANGED
// ===========================================================================
#define FA_STAGE 65536     // Kh 0 / Kl 16K / Vh 32K / Vl 48K
#define FA_SMEM (32768 + 2 * FA_STAGE + 2048)

__global__ __launch_bounds__(256, 1) void fused_attn2(
    const __nv_bfloat16* __restrict__ Qh, const __nv_bfloat16* __restrict__ Ql,
    const __nv_bfloat16* __restrict__ Kh, const __nv_bfloat16* __restrict__ Kl,
    const __nv_bfloat16* __restrict__ Vh, const __nv_bfloat16* __restrict__ Vl,
    float* __restrict__ attn,
    __nv_bfloat16* __restrict__ Oh, __nv_bfloat16* __restrict__ Ol)
{
    extern __shared__ char smc[];
    const uint32_t sb = smem_u32(smc);
    const int t = threadIdx.x, lane = t & 31, wid = t >> 5;
    const int m0 = blockIdx.x * 128, bh = blockIdx.y;
    const int wm = wid & 3, wc = wid >> 2;     // 4 M x 2 C
    const int mrow = wm * 32, ncol = wc * 64;
    const size_t gB = (size_t)bh * SS * DH;

    const uint32_t sQh = sb, sQl = sb + 16384;
    float* zred = (float*)(smc + 32768 + 2 * FA_STAGE);   // [2][128]

    const int rBn = (lane & 7) + ((lane & 16) >> 1);
    const int cB  = ((lane & 8) << 1);
    const int rV  = (lane & 7) + (lane & 8);
    const int cV  = (lane >> 4) * 16;
    const int l15 = lane & 15, l16 = lane & 16;

    // Q loads
    #pragma unroll
    for (int i = 0; i < 4; i++) {
        int idx = t + i * 256;
        int row = idx >> 3, ck = idx & 7;
        uint32_t so = sw128((uint32_t)(row * 128 + ck * 16));
        size_t g = gB + (size_t)(m0 + row) * DH + ck * 8;
        cp16(sQh + so, Qh + g);
        cp16(sQl + so, Ql + g);
    }

    auto prefKh = [&](int kt) {
        uint32_t base = sb + 32768 + (uint32_t)(kt & 1) * FA_STAGE;
        #pragma unroll
        for (int i = 0; i < 4; i++) {
            int idx = t + i * 256;
            int row = idx >> 3, ck = idx & 7;
            uint32_t so = sw128((uint32_t)(row * 128 + ck * 16));
            cp16(base + so, Kh + gB + (size_t)(kt * 128 + row) * DH + ck * 8);
        }
        cp_commit();
    };
    auto prefKV = [&](int kt) {
        uint32_t base = sb + 32768 + (uint32_t)(kt & 1) * FA_STAGE;
        #pragma unroll
        for (int i = 0; i < 4; i++) {
            int idx = t + i * 256;
            int row = idx >> 3, ck = idx & 7;
            uint32_t so = sw128((uint32_t)(row * 128 + ck * 16));
            size_t g = gB + (size_t)(kt * 128 + row) * DH + ck * 8;
            cp16(base + so, Kh + g);
            cp16(base + 16384 + so, Kl + g);
            cp16(base + 32768 + so, Vh + g);
            cp16(base + 49152 + so, Vl + g);
        }
        cp_commit();
    };

    prefKh(0);
    prefKh(1);

    // ------------------- Pass A: Z sums -------------------
    float zs[2][2] = {};
    for (int kt = 0; kt < 16; kt++) {
        if (kt < 15) asm volatile("cp.async.wait_group 1;" ::: "memory");
        else         asm volatile("cp.async.wait_group 0;" ::: "memory");
        __syncthreads();
        uint32_t kb = sb + 32768 + (uint32_t)(kt & 1) * FA_STAGE;

        float acc[2][8][4] = {};
        #pragma unroll
        for (int kg = 0; kg < 4; kg++) {
            uint32_t kf[4][4];
            #pragma unroll
            for (int j = 0; j < 4; j++) {
                uint32_t offB = sw128((uint32_t)((ncol + j * 16 + rBn) * 128 + kg * 32 + cB));
                ldsm_x4(kf[j][0], kf[j][1], kf[j][2], kf[j][3], kb + offB);
            }
            #pragma unroll
            for (int im = 0; im < 2; im++) {
                uint32_t offA = sw128((uint32_t)((mrow + im * 16 + l15) * 128 + kg * 32 + l16));
                uint32_t ah[4];
                ldsm_x4(ah[0], ah[1], ah[2], ah[3], sQh + offA);
                #pragma unroll
                for (int j = 0; j < 4; j++) {
                    mma16816(acc[im][2*j],   ah, &kf[j][0]);
                    mma16816(acc[im][2*j+1], ah, &kf[j][2]);
                }
            }
        }
        #pragma unroll
        for (int im = 0; im < 2; im++)
            #pragma unroll
            for (int nt = 0; nt < 8; nt++) {
                zs[im][0] += fast_exp2(acc[im][nt][0]) + fast_exp2(acc[im][nt][1]);
                zs[im][1] += fast_exp2(acc[im][nt][2]) + fast_exp2(acc[im][nt][3]);
            }
        __syncthreads();
        if (kt + 2 < 16) prefKh(kt + 2);
    }

    #pragma unroll
    for (int im = 0; im < 2; im++) {
        zs[im][0] += __shfl_xor_sync(0xffffffffu, zs[im][0], 1);
        zs[im][0] += __shfl_xor_sync(0xffffffffu, zs[im][0], 2);
        zs[im][1] += __shfl_xor_sync(0xffffffffu, zs[im][1], 1);
        zs[im][1] += __shfl_xor_sync(0xffffffffu, zs[im][1], 2);
    }
    if ((lane & 3) == 0) {
        int r0 = mrow + (lane >> 2);
        zred[wc * 128 + r0]      = zs[0][0];
        zred[wc * 128 + r0 + 8]  = zs[0][1];
        zred[wc * 128 + r0 + 16] = zs[1][0];
        zred[wc * 128 + r0 + 24] = zs[1][1];
    }
    __syncthreads();
    float invZ[2][2];
    {
        int r0 = mrow + (lane >> 2);
        invZ[0][0] = 1.0f / (zred[r0]      + zred[128 + r0]);
        invZ[0][1] = 1.0f / (zred[r0 + 8]  + zred[128 + r0 + 8]);
        invZ[1][0] = 1.0f / (zred[r0 + 16] + zred[128 + r0 + 16]);
        invZ[1][1] = 1.0f / (zred[r0 + 24] + zred[128 + r0 + 24]);
    }
    __syncthreads();

    prefKV(0);
    prefKV(1);

    // ------------------- Pass B -------------------
    float o[2][8][4] = {};

    for (int kt = 0; kt < 16; kt++) {
        if (kt < 15) asm volatile("cp.async.wait_group 1;" ::: "memory");
        else         asm volatile("cp.async.wait_group 0;" ::: "memory");
        __syncthreads();
        uint32_t kb = sb + 32768 + (uint32_t)(kt & 1) * FA_STAGE;

        float acc[2][8][4] = {};
        #pragma unroll
        for (int kg = 0; kg < 4; kg++) {
            uint32_t kfh[4][4], kfl[4][4];
            #pragma unroll
            for (int j = 0; j < 4; j++) {
                uint32_t offB = sw128((uint32_t)((ncol + j * 16 + rBn) * 128 + kg * 32 + cB));
                ldsm_x4(kfh[j][0], kfh[j][1], kfh[j][2], kfh[j][3], kb + offB);
                ldsm_x4(kfl[j][0], kfl[j][1], kfl[j][2], kfl[j][3], kb + 16384 + offB);
            }
            #pragma unroll
            for (int im = 0; im < 2; im++) {
                uint32_t offA = sw128((uint32_t)((mrow + im * 16 + l15) * 128 + kg * 32 + l16));
                uint32_t ah[4], al[4];
                ldsm_x4(ah[0], ah[1], ah[2], ah[3], sQh + offA);
                ldsm_x4(al[0], al[1], al[2], al[3], sQl + offA);
                #pragma unroll
                for (int j = 0; j < 4; j++) {
                    mma16816(acc[im][2*j],   ah, &kfh[j][0]);
                    mma16816(acc[im][2*j+1], ah, &kfh[j][2]);
                }
                #pragma unroll
                for (int j = 0; j < 4; j++) {
                    mma16816(acc[im][2*j],   al, &kfh[j][0]);
                    mma16816(acc[im][2*j+1], al, &kfh[j][2]);
                }
                #pragma unroll
                for (int j = 0; j < 4; j++) {
                    mma16816(acc[im][2*j],   ah, &kfl[j][0]);
                    mma16816(acc[im][2*j+1], ah, &kfl[j][2]);
                }
            }
        }

        // exp + attn store
        #pragma unroll
        for (int im = 0; im < 2; im++) {
            const size_t ar0 = (size_t)bh * SS + m0 + mrow + im * 16 + (lane >> 2);
            #pragma unroll
            for (int nt = 0; nt < 8; nt++) {
                float p0 = fast_exp2(acc[im][nt][0]) * invZ[im][0];
                float p1 = fast_exp2(acc[im][nt][1]) * invZ[im][0];
                float p2 = fast_exp2(acc[im][nt][2]) * invZ[im][1];
                float p3 = fast_exp2(acc[im][nt][3]) * invZ[im][1];
                acc[im][nt][0] = p0; acc[im][nt][1] = p1;
                acc[im][nt][2] = p2; acc[im][nt][3] = p3;
                int col = kt * 128 + ncol + nt * 8 + (lane & 3) * 2;
                *(float2*)&attn[ar0 * SS + col]       = make_float2(p0, p1);
                *(float2*)&attn[(ar0 + 8) * SS + col] = make_float2(p2, p3);
            }
        }

        // PV
        #pragma unroll
        for (int kg = 0; kg < 4; kg++) {
            uint32_t vfh[4][4], vfl[4][4];
            #pragma unroll
            for (int j = 0; j < 4; j++) {
                uint32_t offV = sw128((uint32_t)((ncol + kg * 16 + rV) * 128 + j * 32 + cV));
                ldsm_x4t(vfh[j][0], vfh[j][1], vfh[j][2], vfh[j][3], kb + 32768 + offV);
                ldsm_x4t(vfl[j][0], vfl[j][1], vfl[j][2], vfl[j][3], kb + 49152 + offV);
            }
            #pragma unroll
            for (int im = 0; im < 2; im++) {
                uint32_t ph[4], pl[4];
                #pragma unroll
                for (int half = 0; half < 2; half++) {
                    float* a4 = acc[im][2 * kg + half];
                    uint32_t h0 = pack_bf16x2(a4[0], a4[1]);
                    uint32_t h1 = pack_bf16x2(a4[2], a4[3]);
                    ph[half*2 + 0] = h0;
                    ph[half*2 + 1] = h1;
                    pl[half*2 + 0] = pack_bf16x2(a4[0] - __uint_as_float(h0 << 16),
                                                 a4[1] - __uint_as_float(h0 & 0xffff0000u));
                    pl[half*2 + 1] = pack_bf16x2(a4[2] - __uint_as_float(h1 << 16),
                                                 a4[3] - __uint_as_float(h1 & 0xffff0000u));
                }
                #pragma unroll
                for (int j = 0; j < 4; j++) {
                    mma16816(o[im][2*j],   ph, &vfh[j][0]);
                    mma16816(o[im][2*j+1], ph, &vfh[j][2]);
                }
                #pragma unroll
                for (int j = 0; j < 4; j++) {
                    mma16816(o[im][2*j],   pl, &vfh[j][0]);
                    mma16816(o[im][2*j+1], pl, &vfh[j][2]);
                }
                #pragma unroll
                for (int j = 0; j < 4; j++) {
                    mma16816(o[im][2*j],   ph, &vfl[j][0]);
                    mma16816(o[im][2*j+1], ph, &vfl[j][2]);
                }
            }
        }
        __syncthreads();
        if (kt + 2 < 16) prefKV(kt + 2);
    }

    // ------------------- O reduction + epilogue -------------------
    __syncthreads();
    float* ored = (float*)(smc + 32768);   // reuse stage area: [128][64]
    if (wc == 1) {
        #pragma unroll
        for (int im = 0; im < 2; im++)
            #pragma unroll
            for (int nt = 0; nt < 8; nt++) {
                int row = mrow + im * 16 + (lane >> 2);
                int col = nt * 8 + (lane & 3) * 2;
                *(float2*)&ored[row * 64 + col] = make_float2(o[im][nt][0], o[im][nt][1]);
                *(float2*)&ored[(row + 8) * 64 + col] = make_float2(o[im][nt][2], o[im][nt][3]);
            }
    }
    __syncthreads();
    if (wc == 0) {
        const int b = bh >> 4, h = bh & 15;
        #pragma unroll
        for (int im = 0; im < 2; im++)
            #pragma unroll
            for (int nt = 0; nt < 8; nt++) {
                int row = mrow + im * 16 + (lane >> 2);
                int col = nt * 8 + (lane & 3) * 2;
                float2 a0 = *(float2*)&ored[row * 64 + col];
                float2 a1 = *(float2*)&ored[(row + 8) * 64 + col];
                float v0 = o[im][nt][0] + a0.x, v1 = o[im][nt][1] + a0.y;
                float v2 = o[im][nt][2] + a1.x, v3 = o[im][nt][3] + a1.y;
                size_t gr = (size_t)(b * SS + m0 + row);
                int gc = h * 64 + col;
                size_t off0 = gr * DD + gc;
                size_t off1 = (gr + 8) * DD + gc;
                uint32_t p0 = pack_bf16x2(v0, v1);
                uint32_t p1 = pack_bf16x2(v2, v3);
                *(uint32_t*)&Oh[off0] = p0;
                *(uint32_t*)&Oh[off1] = p1;
                uint32_t q0 = pack_bf16x2(v0 - __uint_as_float(p0 << 16),
                                          v1 - __uint_as_float(p0 & 0xffff0000u));
                uint32_t q1 = pack_bf16x2(v2 - __uint_as_float(p1 << 16),
                                          v3 - __uint_as_float(p1 & 0xffff0000u));
                *(uint32_t*)&Ol[off0] = q0;
                *(uint32_t*)&Ol[off1] = q1;
            }
    }
}

// ===========================================================================
extern "C" void kernel_launch(void* const* d_in, const int* in_sizes, int n_in,
                              void* d_out, int out_size)
{
    const float* q  = (const float*)d_in[0];
    const float* k  = (const float*)d_in[1];
    const float* v  = (const float*)d_in[2];
    const float* Wq = (const float*)d_in[4];
    const float* bq = (const float*)d_in[5];
    const float* Wk = (const float*)d_in[6];
    const float* bk = (const float*)d_in[7];
    const float* Wv = (const float*)d_in[8];
    const float* bv = (const float*)d_in[9];
    const float* Wo = (const float*)d_in[10];
    const float* bo = (const float*)d_in[11];

    float* out_ptr  = (float*)d_out;
    float* attn_ptr = (float*)d_out + OUT_ELEMS;

    __nv_bfloat16 *gAh, *gAl;
    __nv_bfloat16 *gSqh, *gSql, *gSkh, *gSkl, *gSvh, *gSvl;
    __nv_bfloat16 *gW1h, *gW1l, *gW2h, *gW2l, *gW3h, *gW3l, *gW4h, *gW4l;
    __nv_bfloat16 *gQh, *gQl, *gKh, *gKl, *gVh, *gVl;
    cudaGetSymbolAddress((void**)&gAh, g_Ah);
    cudaGetSymbolAddress((void**)&gAl, g_Al);
    cudaGetSymbolAddress((void**)&gSqh, g_Sqh); cudaGetSymbolAddress((void**)&gSql, g_Sql);
    cudaGetSymbolAddress((void**)&gSkh, g_Skh); cudaGetSymbolAddress((void**)&gSkl, g_Skl);
    cudaGetSymbolAddress((void**)&gSvh, g_Svh); cudaGetSymbolAddress((void**)&gSvl, g_Svl);
    cudaGetSymbolAddress((void**)&gW1h, g_W1h); cudaGetSymbolAddress((void**)&gW1l, g_W1l);
    cudaGetSymbolAddress((void**)&gW2h, g_W2h); cudaGetSymbolAddress((void**)&gW2l, g_W2l);
    cudaGetSymbolAddress((void**)&gW3h, g_W3h); cudaGetSymbolAddress((void**)&gW3l, g_W3l);
    cudaGetSymbolAddress((void**)&gW4h, g_W4h); cudaGetSymbolAddress((void**)&gW4l, g_W4l);
    cudaGetSymbolAddress((void**)&gQh, g_Qh); cudaGetSymbolAddress((void**)&gQl, g_Ql);
    cudaGetSymbolAddress((void**)&gKh, g_Kh); cudaGetSymbolAddress((void**)&gKl, g_Kl);
    cudaGetSymbolAddress((void**)&gVh, g_Vh); cudaGetSymbolAddress((void**)&gVl, g_Vl);

    cudaFuncSetAttribute(gemm_hmma_qkv, cudaFuncAttributeMaxDynamicSharedMemorySize,
                         SM_GEMM_BYTES);
    cudaFuncSetAttribute(gemm_hmma_out, cudaFuncAttributeMaxDynamicSharedMemorySize,
                         SM_GEMM_BYTES);
    cudaFuncSetAttribute(fused_attn2, cudaFuncAttributeMaxDynamicSharedMemorySize,
                         FA_SMEM);

    const int NA4 = (int)(OUT_ELEMS / 4);
    const int NW4 = DD * DD / 4;

    // Batched splits: q, k, v, Wq, Wk, Wv, Wo
    SplitJobs jobs;
    jobs.j[0] = { (const float4*)q,  (uint2*)gSqh, (uint2*)gSql, NA4 };
    jobs.j[1] = { (const float4*)k,  (uint2*)gSkh, (uint2*)gSkl, NA4 };
    jobs.j[2] = { (const float4*)v,  (uint2*)gSvh, (uint2*)gSvl, NA4 };
    jobs.j[3] = { (const float4*)Wq, (uint2*)gW1h, (uint2*)gW1l, NW4 };
    jobs.j[4] = { (const float4*)Wk, (uint2*)gW2h, (uint2*)gW2l, NW4 };
    jobs.j[5] = { (const float4*)Wv, (uint2*)gW3h, (uint2*)gW3l, NW4 };
    jobs.j[6] = { (const float4*)Wo, (uint2*)gW4h, (uint2*)gW4l, NW4 };
    split_batch<<<dim3((NA4 + 255) / 256, 7), 256>>>(jobs);

    // Merged Q/K/V projections (Q scaled by 0.125*log2e)
    const float QSCALE = 0.125f * 1.4426950408889634f;
    GemmJobs gj;
    gj.j[0] = { gSqh, gSql, gW1h, gW1l, bq, gQh, gQl, QSCALE };
    gj.j[1] = { gSkh, gSkl, gW2h, gW2l, bk, gKh, gKl, 1.0f };
    gj.j[2] = { gSvh, gSvl, gW3h, gW3l, bv, gVh, gVl, 1.0f };
    dim3 gp3(DD / 128, NROW / 128, 3);
    gemm_hmma_qkv<<<gp3, 512, SM_GEMM_BYTES>>>(gj);

    // Fused attention (writes bf16-split O directly)
    dim3 gf(SS / 128, BB * HH);
    fused_attn2<<<gf, 256, FA_SMEM>>>(gQh, gQl, gKh, gKl, gVh, gVl, attn_ptr, gAh, gAl);

    // Output projection
    dim3 gp(DD / 128, NROW / 128);
    gemm_hmma_out<<<gp, 512, SM_GEMM_BYTES>>>(gAh, gAl, gW4h, gW4l, bo, out_ptr);
}

// round 14
// speedup vs baseline: 1.0254x; 1.0254x over previous
#include <cuda_runtime.h>
#include <cuda_bf16.h>
#include <math.h>
#include <stdint.h>

#define BB 2
#define SS 2048
#define DD 1024
#define HH 16
#define DH 64
#define NROW (BB*SS)
#define OUT_ELEMS ((size_t)BB*SS*DD)

// Scratch (device globals)
__device__ __nv_bfloat16 g_Ah[NROW*DD];
__device__ __nv_bfloat16 g_Al[NROW*DD];
__device__ __nv_bfloat16 g_Sqh[NROW*DD], g_Sql[NROW*DD];
__device__ __nv_bfloat16 g_Skh[NROW*DD], g_Skl[NROW*DD];
__device__ __nv_bfloat16 g_Svh[NROW*DD], g_Svl[NROW*DD];
__device__ __nv_bfloat16 g_W1h[DD*DD], g_W1l[DD*DD];
__device__ __nv_bfloat16 g_W2h[DD*DD], g_W2l[DD*DD];
__device__ __nv_bfloat16 g_W3h[DD*DD], g_W3l[DD*DD];
__device__ __nv_bfloat16 g_W4h[DD*DD], g_W4l[DD*DD];
__device__ __nv_bfloat16 g_Qh[NROW*DD], g_Ql[NROW*DD];
__device__ __nv_bfloat16 g_Kh[NROW*DD], g_Kl[NROW*DD];
__device__ __nv_bfloat16 g_Vh[NROW*DD], g_Vl[NROW*DD];

// ===========================================================================
// helpers
// ===========================================================================
__device__ __forceinline__ float fast_exp2(float x) {
    float r;
    asm("ex2.approx.f32 %0, %1;" : "=f"(r) : "f"(x));
    return r;
}
__device__ __forceinline__ uint32_t smem_u32(const void* p) {
    uint32_t a;
    asm("{ .reg .u64 t; cvta.to.shared.u64 t, %1; cvt.u32.u64 %0, t; }"
        : "=r"(a) : "l"(p));
    return a;
}
__device__ __forceinline__ uint32_t sw128(uint32_t off) {
    return off ^ ((off >> 3) & 0x70);
}
__device__ __forceinline__ void cp16(uint32_t dst, const void* src) {
    asm volatile("cp.async.cg.shared.global [%0], [%1], 16;"
                 :: "r"(dst), "l"(src));
}
__device__ __forceinline__ void cp_commit() {
    asm volatile("cp.async.commit_group;" ::: "memory");
}
__device__ __forceinline__ void ldsm_x4(uint32_t& r0, uint32_t& r1,
                                        uint32_t& r2, uint32_t& r3, uint32_t a) {
    asm volatile("ldmatrix.sync.aligned.m8n8.x4.shared.b16 {%0,%1,%2,%3}, [%4];"
                 : "=r"(r0), "=r"(r1), "=r"(r2), "=r"(r3) : "r"(a));
}
__device__ __forceinline__ void ldsm_x4t(uint32_t& r0, uint32_t& r1,
                                         uint32_t& r2, uint32_t& r3, uint32_t a) {
    asm volatile("ldmatrix.sync.aligned.m8n8.x4.trans.shared.b16 {%0,%1,%2,%3}, [%4];"
                 : "=r"(r0), "=r"(r1), "=r"(r2), "=r"(r3) : "r"(a));
}
__device__ __forceinline__ void mma16816(float* d, const uint32_t* a, const uint32_t* b) {
    asm volatile(
        "mma.sync.aligned.m16n8k16.row.col.f32.bf16.bf16.f32 "
        "{%0,%1,%2,%3}, {%4,%5,%6,%7}, {%8,%9}, {%0,%1,%2,%3};"
        : "+f"(d[0]), "+f"(d[1]), "+f"(d[2]), "+f"(d[3])
        : "r"(a[0]), "r"(a[1]), "r"(a[2]), "r"(a[3]), "r"(b[0]), "r"(b[1]));
}
__device__ __forceinline__ uint32_t pack_bf16x2(float lo, float hi) {
    uint32_t r;
    asm("cvt.rn.bf16x2.f32 %0, %1, %2;" : "=r"(r) : "f"(hi), "f"(lo));
    return r;
}

// ===========================================================================
// batched fp32 -> bf16 hi/lo split (4 float4 per thread for MLP)
// ===========================================================================
struct SplitJob { const float4* in; uint2* hi; uint2* lo; int n4; };
struct SplitJobs { SplitJob j[7]; };

__device__ __forceinline__ void do_split(const float4* in, uint2* hi, uint2* lo, int i) {
    float4 v = in[i];
    float f[4] = {v.x, v.y, v.z, v.w};
    uint16_t h[4], l[4];
    #pragma unroll
    for (int j = 0; j < 4; j++) {
        __nv_bfloat16 hb = __float2bfloat16(f[j]);
        __nv_bfloat16 lb = __float2bfloat16(f[j] - __bfloat162float(hb));
        h[j] = __bfloat16_as_ushort(hb);
        l[j] = __bfloat16_as_ushort(lb);
    }
    hi[i] = make_uint2((uint32_t)h[0] | ((uint32_t)h[1] << 16),
                       (uint32_t)h[2] | ((uint32_t)h[3] << 16));
    lo[i] = make_uint2((uint32_t)l[0] | ((uint32_t)l[1] << 16),
                       (uint32_t)l[2] | ((uint32_t)l[3] << 16));
}

__global__ __launch_bounds__(256) void split_batch(SplitJobs jobs) {
    SplitJob jb = jobs.j[blockIdx.y];
    int base = blockIdx.x * 1024 + threadIdx.x;
    #pragma unroll
    for (int it = 0; it < 4; it++) {
        int i = base + it * 256;
        if (i < jb.n4) do_split(jb.in, jb.hi, jb.lo, i);
    }
}

// ===========================================================================
// HMMA bf16-split GEMM core (R12 best: 256 threads, 8 warps 2x4)
// ===========================================================================
#define NTS 16
#define GSTAGE 65536
#define SM_GEMM_BYTES 131072

struct GemmJob {
    const __nv_bfloat16 *ah, *al, *wh, *wl;
    const float* bias;
    __nv_bfloat16 *ch, *cl;
    float scale;
};
struct GemmJobs { GemmJob j[3]; };

__device__ __forceinline__ void gemm_core(
    const __nv_bfloat16* __restrict__ Agh, const __nv_bfloat16* __restrict__ Agl,
    const __nv_bfloat16* __restrict__ Wgh, const __nv_bfloat16* __restrict__ Wgl,
    const float* __restrict__ bias, float* __restrict__ C,
    __nv_bfloat16* __restrict__ Ch, __nv_bfloat16* __restrict__ Cl,
    float scale, int mode, char* smc)
{
    const uint32_t sb = smem_u32(smc);
    const int t = threadIdx.x;
    const int lane = t & 31;
    const int wid = t >> 5;
    const int wm = wid & 1;
    const int wn = wid >> 1;
    const int m0 = blockIdx.y * 128;
    const int n0 = blockIdx.x * 128;

    float acc[4][4][4] = {};

    auto prefetch = [&](int s) {
        const int ksl = s * 64;
        const uint32_t base = sb + (s & 1) * GSTAGE;
        #pragma unroll
        for (int i = 0; i < 4; i++) {
            int idx = t + i * 256;
            int row = idx >> 3, ck = idx & 7;
            uint32_t so = sw128((uint32_t)(row * 128 + ck * 16));
            size_t g = (size_t)(m0 + row) * DD + ksl + ck * 8;
            cp16(base + so, Agh + g);
            cp16(base + 16384 + so, Agl + g);
        }
        #pragma unroll
        for (int i = 0; i < 4; i++) {
            int idx = t + i * 256;
            int kr = idx >> 4, cn = idx & 15;
            uint32_t so = (uint32_t)((cn >> 3) * 8192)
                        + sw128((uint32_t)(kr * 128 + (cn & 7) * 16));
            size_t g = (size_t)(ksl + kr) * DD + n0 + cn * 8;
            cp16(base + 32768 + so, Wgh + g);
            cp16(base + 49152 + so, Wgl + g);
        }
        cp_commit();
    };

    prefetch(0);
    prefetch(1);

    for (int s = 0; s < NTS; s++) {
        if (s < NTS - 1) asm volatile("cp.async.wait_group 1;" ::: "memory");
        else             asm volatile("cp.async.wait_group 0;" ::: "memory");
        __syncthreads();

        const uint32_t aB  = sb + (s & 1) * GSTAGE;
        const uint32_t alB = aB + 16384;
        const uint32_t bhB = aB + 32768;
        const uint32_t blB = aB + 49152;

        const int lg = lane >> 3, l7 = lane & 7;

        #pragma unroll
        for (int ks = 0; ks < 4; ks++) {
            const int kb = ks * 32;
            uint32_t bh[4][2], bl[4][2];
            #pragma unroll
            for (int jj = 0; jj < 2; jj++) {
                int nloc = wn * 32 + jj * 16;
                uint32_t stb = (uint32_t)((nloc >> 6) * 8192);
                int ncol = nloc & 63;
                int krow = ks * 16 + (lg & 1) * 8 + l7;
                uint32_t off = stb + sw128((uint32_t)(krow * 128 + ncol * 2 + (lg >> 1) * 16));
                uint32_t r0, r1, r2, r3;
                ldsm_x4t(r0, r1, r2, r3, bhB + off);
                bh[jj*2+0][0] = r0; bh[jj*2+0][1] = r1;
                bh[jj*2+1][0] = r2; bh[jj*2+1][1] = r3;
                ldsm_x4t(r0, r1, r2, r3, blB + off);
                bl[jj*2+0][0] = r0; bl[jj*2+0][1] = r1;
                bl[jj*2+1][0] = r2; bl[jj*2+1][1] = r3;
            }
            #pragma unroll
            for (int im = 0; im < 4; im++) {
                int arow = wm * 64 + im * 16 + (lg & 1) * 8 + l7;
                uint32_t off = sw128((uint32_t)(arow * 128 + kb + (lg >> 1) * 16));
                uint32_t ah[4], al[4];
                ldsm_x4(ah[0], ah[1], ah[2], ah[3], aB + off);
                ldsm_x4(al[0], al[1], al[2], al[3], alB + off);
                #pragma unroll
                for (int jn = 0; jn < 4; jn++) mma16816(acc[im][jn], ah, bh[jn]);
                #pragma unroll
                for (int jn = 0; jn < 4; jn++) mma16816(acc[im][jn], ah, bl[jn]);
                #pragma unroll
                for (int jn = 0; jn < 4; jn++) mma16816(acc[im][jn], al, bh[jn]);
            }
        }
        __syncthreads();
        if (s + 2 < NTS) prefetch(s + 2);
    }

    #pragma unroll
    for (int im = 0; im < 4; im++) {
        int r0 = m0 + wm * 64 + im * 16 + (lane >> 2);
        #pragma unroll
        for (int jn = 0; jn < 4; jn++) {
            int col = n0 + wn * 32 + jn * 8 + (lane & 3) * 2;
            float b0 = bias[col], b1 = bias[col + 1];
            float v00 = acc[im][jn][0] + b0, v01 = acc[im][jn][1] + b1;
            float v10 = acc[im][jn][2] + b0, v11 = acc[im][jn][3] + b1;
            if (mode == 0) {
                *(float2*)&C[(size_t)r0 * DD + col] = make_float2(v00, v01);
                *(float2*)&C[(size_t)(r0 + 8) * DD + col] = make_float2(v10, v11);
            } else {
                v00 *= scale; v01 *= scale; v10 *= scale; v11 *= scale;
                int h = col >> 6, dd = col & 63;
                int b_ = r0 >> 11, s0 = r0 & 2047;
                int b2 = (r0 + 8) >> 11, s1 = (r0 + 8) & 2047;
                size_t off0 = ((size_t)(b_ * HH + h) * SS + s0) * DH + dd;
                size_t off1 = ((size_t)(b2 * HH + h) * SS + s1) * DH + dd;
                uint32_t p0 = pack_bf16x2(v00, v01);
                uint32_t p1 = pack_bf16x2(v10, v11);
                *(uint32_t*)&Ch[off0] = p0;
                *(uint32_t*)&Ch[off1] = p1;
                uint32_t q0 = pack_bf16x2(v00 - __uint_as_float(p0 << 16),
                                          v01 - __uint_as_float(p0 & 0xffff0000u));
                uint32_t q1 = pack_bf16x2(v10 - __uint_as_float(p1 << 16),
                                          v11 - __uint_as_float(p1 & 0xffff0000u));
                *(uint32_t*)&Cl[off0] = q0;
                *(uint32_t*)&Cl[off1] = q1;
            }
        }
    }
}

__global__ __launch_bounds__(256, 1) void gemm_hmma_qkv(GemmJobs jobs) {
    extern __shared__ char smc[];
    GemmJob jb = jobs.j[blockIdx.z];
    gemm_core(jb.ah, jb.al, jb.wh, jb.wl, jb.bias, nullptr,
              jb.ch, jb.cl, jb.scale, 2, smc);
}

__global__ __launch_bounds__(256, 1) void gemm_hmma_out(
    const __nv_bfloat16* __restrict__ Agh, const __nv_bfloat16* __restrict__ Agl,
    const __nv_bfloat16* __restrict__ Wgh, const __nv_bfloat16* __restrict__ Wgl,
    const float* __restrict__ bias, float* __restrict__ C)
{
    extern __shared__ char smc[];
    gemm_core(Agh, Agl, Wgh, Wgl, bias, C, nullptr, nullptr, 1.0f, 0, smc);
}

// ===========================================================================
// Fused attention (4Mx2C warp tiling). Pass A now processes 256 K rows
// per iteration (8 iterations, 32KB stages) to halve sync overhead.
// ===========================================================================
#define FA_STAGE 65536     // pass B: Kh 0 / Kl 16K / Vh 32K / Vl 48K
#define FA_SMEM (32768 + 2 * FA_STAGE + 2048)

__global__ __launch_bounds__(256, 1) void fused_attn2(
    const __nv_bfloat16* __restrict__ Qh, const __nv_bfloat16* __restrict__ Ql,
    const __nv_bfloat16* __restrict__ Kh, const __nv_bfloat16* __restrict__ Kl,
    const __nv_bfloat16* __restrict__ Vh, const __nv_bfloat16* __restrict__ Vl,
    float* __restrict__ attn,
    __nv_bfloat16* __restrict__ Oh, __nv_bfloat16* __restrict__ Ol)
{
    extern __shared__ char smc[];
    const uint32_t sb = smem_u32(smc);
    const int t = threadIdx.x, lane = t & 31, wid = t >> 5;
    const int m0 = blockIdx.x * 128, bh = blockIdx.y;
    const int wm = wid & 3, wc = wid >> 2;     // 4 M x 2 C
    const int mrow = wm * 32, ncol = wc * 64;
    const size_t gB = (size_t)bh * SS * DH;

    const uint32_t sQh = sb, sQl = sb + 16384;
    float* zred = (float*)(smc + 32768 + 2 * FA_STAGE);   // [2][128]

    const int rBn = (lane & 7) + ((lane & 16) >> 1);
    const int cB  = ((lane & 8) << 1);
    const int rV  = (lane & 7) + (lane & 8);
    const int cV  = (lane >> 4) * 16;
    const int l15 = lane & 15, l16 = lane & 16;

    // Q loads
    #pragma unroll
    for (int i = 0; i < 4; i++) {
        int idx = t + i * 256;
        int row = idx >> 3, ck = idx & 7;
        uint32_t so = sw128((uint32_t)(row * 128 + ck * 16));
        size_t g = gB + (size_t)(m0 + row) * DH + ck * 8;
        cp16(sQh + so, Qh + g);
        cp16(sQl + so, Ql + g);
    }

    // pass A: 256 K rows (32KB Kh) per stage
    auto prefKh2 = [&](int it) {
        uint32_t base = sb + 32768 + (uint32_t)(it & 1) * 32768;
        #pragma unroll
        for (int i = 0; i < 8; i++) {
            int idx = t + i * 256;
            int row = idx >> 3, ck = idx & 7;
            uint32_t so = sw128((uint32_t)(row * 128 + ck * 16));
            cp16(base + so, Kh + gB + (size_t)(it * 256 + row) * DH + ck * 8);
        }
        cp_commit();
    };
    auto prefKV = [&](int kt) {
        uint32_t base = sb + 32768 + (uint32_t)(kt & 1) * FA_STAGE;
        #pragma unroll
        for (int i = 0; i < 4; i++) {
            int idx = t + i * 256;
            int row = idx >> 3, ck = idx & 7;
            uint32_t so = sw128((uint32_t)(row * 128 + ck * 16));
            size_t g = gB + (size_t)(kt * 128 + row) * DH + ck * 8;
            cp16(base + so, Kh + g);
            cp16(base + 16384 + so, Kl + g);
            cp16(base + 32768 + so, Vh + g);
            cp16(base + 49152 + so, Vl + g);
        }
        cp_commit();
    };

    prefKh2(0);
    prefKh2(1);

    // ------------------- Pass A: Z sums (8 iterations of 256 rows) -------------------
    float zs[2][2] = {};
    for (int it = 0; it < 8; it++) {
        if (it < 7) asm volatile("cp.async.wait_group 1;" ::: "memory");
        else        asm volatile("cp.async.wait_group 0;" ::: "memory");
        __syncthreads();
        uint32_t kb0 = sb + 32768 + (uint32_t)(it & 1) * 32768;

        #pragma unroll
        for (int half = 0; half < 2; half++) {
            uint32_t kb = kb0 + (uint32_t)half * 16384;
            float acc[2][8][4] = {};
            #pragma unroll
            for (int kg = 0; kg < 4; kg++) {
                uint32_t kf[4][4];
                #pragma unroll
                for (int j = 0; j < 4; j++) {
                    uint32_t offB = sw128((uint32_t)((ncol + j * 16 + rBn) * 128 + kg * 32 + cB));
                    ldsm_x4(kf[j][0], kf[j][1], kf[j][2], kf[j][3], kb + offB);
                }
                #pragma unroll
                for (int im = 0; im < 2; im++) {
                    uint32_t offA = sw128((uint32_t)((mrow + im * 16 + l15) * 128 + kg * 32 + l16));
                    uint32_t ah[4];
                    ldsm_x4(ah[0], ah[1], ah[2], ah[3], sQh + offA);
                    #pragma unroll
                    for (int j = 0; j < 4; j++) {
                        mma16816(acc[im][2*j],   ah, &kf[j][0]);
                        mma16816(acc[im][2*j+1], ah, &kf[j][2]);
                    }
                }
            }
            #pragma unroll
            for (int im = 0; im < 2; im++)
                #pragma unroll
                for (int nt = 0; nt < 8; nt++) {
                    zs[im][0] += fast_exp2(acc[im][nt][0]) + fast_exp2(acc[im][nt][1]);
                    zs[im][1] += fast_exp2(acc[im][nt][2]) + fast_exp2(acc[im][nt][3]);
                }
        }
        __syncthreads();
        if (it + 2 < 8) prefKh2(it + 2);
    }

    #pragma unroll
    for (int im = 0; im < 2; im++) {
        zs[im][0] += __shfl_xor_sync(0xffffffffu, zs[im][0], 1);
        zs[im][0] += __shfl_xor_sync(0xffffffffu, zs[im][0], 2);
        zs[im][1] += __shfl_xor_sync(0xffffffffu, zs[im][1], 1);
        zs[im][1] += __shfl_xor_sync(0xffffffffu, zs[im][1], 2);
    }
    if ((lane & 3) == 0) {
        int r0 = mrow + (lane >> 2);
        zred[wc * 128 + r0]      = zs[0][0];
        zred[wc * 128 + r0 + 8]  = zs[0][1];
        zred[wc * 128 + r0 + 16] = zs[1][0];
        zred[wc * 128 + r0 + 24] = zs[1][1];
    }
    __syncthreads();
    float invZ[2][2];
    {
        int r0 = mrow + (lane >> 2);
        invZ[0][0] = 1.0f / (zred[r0]      + zred[128 + r0]);
        invZ[0][1] = 1.0f / (zred[r0 + 8]  + zred[128 + r0 + 8]);
        invZ[1][0] = 1.0f / (zred[r0 + 16] + zred[128 + r0 + 16]);
        invZ[1][1] = 1.0f / (zred[r0 + 24] + zred[128 + r0 + 24]);
    }
    __syncthreads();

    prefKV(0);
    prefKV(1);

    // ------------------- Pass B -------------------
    float o[2][8][4] = {};

    for (int kt = 0; kt < 16; kt++) {
        if (kt < 15) asm volatile("cp.async.wait_group 1;" ::: "memory");
        else         asm volatile("cp.async.wait_group 0;" ::: "memory");
        __syncthreads();
        uint32_t kb = sb + 32768 + (uint32_t)(kt & 1) * FA_STAGE;

        float acc[2][8][4] = {};
        #pragma unroll
        for (int kg = 0; kg < 4; kg++) {
            uint32_t kfh[4][4], kfl[4][4];
            #pragma unroll
            for (int j = 0; j < 4; j++) {
                uint32_t offB = sw128((uint32_t)((ncol + j * 16 + rBn) * 128 + kg * 32 + cB));
                ldsm_x4(kfh[j][0], kfh[j][1], kfh[j][2], kfh[j][3], kb + offB);
                ldsm_x4(kfl[j][0], kfl[j][1], kfl[j][2], kfl[j][3], kb + 16384 + offB);
            }
            #pragma unroll
            for (int im = 0; im < 2; im++) {
                uint32_t offA = sw128((uint32_t)((mrow + im * 16 + l15) * 128 + kg * 32 + l16));
                uint32_t ah[4], al[4];
                ldsm_x4(ah[0], ah[1], ah[2], ah[3], sQh + offA);
                ldsm_x4(al[0], al[1], al[2], al[3], sQl + offA);
                #pragma unroll
                for (int j = 0; j < 4; j++) {
                    mma16816(acc[im][2*j],   ah, &kfh[j][0]);
                    mma16816(acc[im][2*j+1], ah, &kfh[j][2]);
                }
                #pragma unroll
                for (int j = 0; j < 4; j++) {
                    mma16816(acc[im][2*j],   al, &kfh[j][0]);
                    mma16816(acc[im][2*j+1], al, &kfh[j][2]);
                }
                #pragma unroll
                for (int j = 0; j < 4; j++) {
                    mma16816(acc[im][2*j],   ah, &kfl[j][0]);
                    mma16816(acc[im][2*j+1], ah, &kfl[j][2]);
                }
            }
        }

        // exp + attn store
        #pragma unroll
        for (int im = 0; im < 2; im++) {
            const size_t ar0 = (size_t)bh * SS + m0 + mrow + im * 16 + (lane >> 2);
            #pragma unroll
            for (int nt = 0; nt < 8; nt++) {
                float p0 = fast_exp2(acc[im][nt][0]) * invZ[im][0];
                float p1 = fast_exp2(acc[im][nt][1]) * invZ[im][0];
                float p2 = fast_exp2(acc[im][nt][2]) * invZ[im][1];
                float p3 = fast_exp2(acc[im][nt][3]) * invZ[im][1];
                acc[im][nt][0] = p0; acc[im][nt][1] = p1;
                acc[im][nt][2] = p2; acc[im][nt][3] = p3;
                int col = kt * 128 + ncol + nt * 8 + (lane & 3) * 2;
                *(float2*)&attn[ar0 * SS + col]       = make_float2(p0, p1);
                *(float2*)&attn[(ar0 + 8) * SS + col] = make_float2(p2, p3);
            }
        }

        // PV
        #pragma unroll
        for (int kg = 0; kg < 4; kg++) {
            uint32_t vfh[4][4], vfl[4][4];
            #pragma unroll
            for (int j = 0; j < 4; j++) {
                uint32_t offV = sw128((uint32_t)((ncol + kg * 16 + rV) * 128 + j * 32 + cV));
                ldsm_x4t(vfh[j][0], vfh[j][1], vfh[j][2], vfh[j][3], kb + 32768 + offV);
                ldsm_x4t(vfl[j][0], vfl[j][1], vfl[j][2], vfl[j][3], kb + 49152 + offV);
            }
            #pragma unroll
            for (int im = 0; im < 2; im++) {
                uint32_t ph[4], pl[4];
                #pragma unroll
                for (int half = 0; half < 2; half++) {
                    float* a4 = acc[im][2 * kg + half];
                    uint32_t h0 = pack_bf16x2(a4[0], a4[1]);
                    uint32_t h1 = pack_bf16x2(a4[2], a4[3]);
                    ph[half*2 + 0] = h0;
                    ph[half*2 + 1] = h1;
                    pl[half*2 + 0] = pack_bf16x2(a4[0] - __uint_as_float(h0 << 16),
                                                 a4[1] - __uint_as_float(h0 & 0xffff0000u));
                    pl[half*2 + 1] = pack_bf16x2(a4[2] - __uint_as_float(h1 << 16),
                                                 a4[3] - __uint_as_float(h1 & 0xffff0000u));
                }
                #pragma unroll
                for (int j = 0; j < 4; j++) {
                    mma16816(o[im][2*j],   ph, &vfh[j][0]);
                    mma16816(o[im][2*j+1], ph, &vfh[j][2]);
                }
                #pragma unroll
                for (int j = 0; j < 4; j++) {
                    mma16816(o[im][2*j],   pl, &vfh[j][0]);
                    mma16816(o[im][2*j+1], pl, &vfh[j][2]);
                }
                #pragma unroll
                for (int j = 0; j < 4; j++) {
                    mma16816(o[im][2*j],   ph, &vfl[j][0]);
                    mma16816(o[im][2*j+1], ph, &vfl[j][2]);
                }
            }
        }
        __syncthreads();
        if (kt + 2 < 16) prefKV(kt + 2);
    }

    // ------------------- O reduction + epilogue -------------------
    __syncthreads();
    float* ored = (float*)(smc + 32768);   // reuse stage area: [128][64]
    if (wc == 1) {
        #pragma unroll
        for (int im = 0; im < 2; im++)
            #pragma unroll
            for (int nt = 0; nt < 8; nt++) {
                int row = mrow + im * 16 + (lane >> 2);
                int col = nt * 8 + (lane & 3) * 2;
                *(float2*)&ored[row * 64 + col] = make_float2(o[im][nt][0], o[im][nt][1]);
                *(float2*)&ored[(row + 8) * 64 + col] = make_float2(o[im][nt][2], o[im][nt][3]);
            }
    }
    __syncthreads();
    if (wc == 0) {
        const int b = bh >> 4, h = bh & 15;
        #pragma unroll
        for (int im = 0; im < 2; im++)
            #pragma unroll
            for (int nt = 0; nt < 8; nt++) {
                int row = mrow + im * 16 + (lane >> 2);
                int col = nt * 8 + (lane & 3) * 2;
                float2 a0 = *(float2*)&ored[row * 64 + col];
                float2 a1 = *(float2*)&ored[(row + 8) * 64 + col];
                float v0 = o[im][nt][0] + a0.x, v1 = o[im][nt][1] + a0.y;
                float v2 = o[im][nt][2] + a1.x, v3 = o[im][nt][3] + a1.y;
                size_t gr = (size_t)(b * SS + m0 + row);
                int gc = h * 64 + col;
                size_t off0 = gr * DD + gc;
                size_t off1 = (gr + 8) * DD + gc;
                uint32_t p0 = pack_bf16x2(v0, v1);
                uint32_t p1 = pack_bf16x2(v2, v3);
                *(uint32_t*)&Oh[off0] = p0;
                *(uint32_t*)&Oh[off1] = p1;
                uint32_t q0 = pack_bf16x2(v0 - __uint_as_float(p0 << 16),
                                          v1 - __uint_as_float(p0 & 0xffff0000u));
                uint32_t q1 = pack_bf16x2(v2 - __uint_as_float(p1 << 16),
                                          v3 - __uint_as_float(p1 & 0xffff0000u));
                *(uint32_t*)&Ol[off0] = q0;
                *(uint32_t*)&Ol[off1] = q1;
            }
    }
}

// ===========================================================================
extern "C" void kernel_launch(void* const* d_in, const int* in_sizes, int n_in,
                              void* d_out, int out_size)
{
    const float* q  = (const float*)d_in[0];
    const float* k  = (const float*)d_in[1];
    const float* v  = (const float*)d_in[2];
    const float* Wq = (const float*)d_in[4];
    const float* bq = (const float*)d_in[5];
    const float* Wk = (const float*)d_in[6];
    const float* bk = (const float*)d_in[7];
    const float* Wv = (const float*)d_in[8];
    const float* bv = (const float*)d_in[9];
    const float* Wo = (const float*)d_in[10];
    const float* bo = (const float*)d_in[11];

    float* out_ptr  = (float*)d_out;
    float* attn_ptr = (float*)d_out + OUT_ELEMS;

    __nv_bfloat16 *gAh, *gAl;
    __nv_bfloat16 *gSqh, *gSql, *gSkh, *gSkl, *gSvh, *gSvl;
    __nv_bfloat16 *gW1h, *gW1l, *gW2h, *gW2l, *gW3h, *gW3l, *gW4h, *gW4l;
    __nv_bfloat16 *gQh, *gQl, *gKh, *gKl, *gVh, *gVl;
    cudaGetSymbolAddress((void**)&gAh, g_Ah);
    cudaGetSymbolAddress((void**)&gAl, g_Al);
    cudaGetSymbolAddress((void**)&gSqh, g_Sqh); cudaGetSymbolAddress((void**)&gSql, g_Sql);
    cudaGetSymbolAddress((void**)&gSkh, g_Skh); cudaGetSymbolAddress((void**)&gSkl, g_Skl);
    cudaGetSymbolAddress((void**)&gSvh, g_Svh); cudaGetSymbolAddress((void**)&gSvl, g_Svl);
    cudaGetSymbolAddress((void**)&gW1h, g_W1h); cudaGetSymbolAddress((void**)&gW1l, g_W1l);
    cudaGetSymbolAddress((void**)&gW2h, g_W2h); cudaGetSymbolAddress((void**)&gW2l, g_W2l);
    cudaGetSymbolAddress((void**)&gW3h, g_W3h); cudaGetSymbolAddress((void**)&gW3l, g_W3l);
    cudaGetSymbolAddress((void**)&gW4h, g_W4h); cudaGetSymbolAddress((void**)&gW4l, g_W4l);
    cudaGetSymbolAddress((void**)&gQh, g_Qh); cudaGetSymbolAddress((void**)&gQl, g_Ql);
    cudaGetSymbolAddress((void**)&gKh, g_Kh); cudaGetSymbolAddress((void**)&gKl, g_Kl);
    cudaGetSymbolAddress((void**)&gVh, g_Vh); cudaGetSymbolAddress((void**)&gVl, g_Vl);

    cudaFuncSetAttribute(gemm_hmma_qkv, cudaFuncAttributeMaxDynamicSharedMemorySize,
                         SM_GEMM_BYTES);
    cudaFuncSetAttribute(gemm_hmma_out, cudaFuncAttributeMaxDynamicSharedMemorySize,
                         SM_GEMM_BYTES);
    cudaFuncSetAttribute(fused_attn2, cudaFuncAttributeMaxDynamicSharedMemorySize,
                         FA_SMEM);

    const int NA4 = (int)(OUT_ELEMS / 4);
    const int NW4 = DD * DD / 4;

    // Batched splits: q, k, v, Wq, Wk, Wv, Wo  (4 float4 per thread)
    SplitJobs jobs;
    jobs.j[0] = { (const float4*)q,  (uint2*)gSqh, (uint2*)gSql, NA4 };
    jobs.j[1] = { (const float4*)k,  (uint2*)gSkh, (uint2*)gSkl, NA4 };
    jobs.j[2] = { (const float4*)v,  (uint2*)gSvh, (uint2*)gSvl, NA4 };
    jobs.j[3] = { (const float4*)Wq, (uint2*)gW1h, (uint2*)gW1l, NW4 };
    jobs.j[4] = { (const float4*)Wk, (uint2*)gW2h, (uint2*)gW2l, NW4 };
    jobs.j[5] = { (const float4*)Wv, (uint2*)gW3h, (uint2*)gW3l, NW4 };
    jobs.j[6] = { (const float4*)Wo, (uint2*)gW4h, (uint2*)gW4l, NW4 };
    split_batch<<<dim3((NA4 + 1023) / 1024, 7), 256>>>(jobs);

    // Merged Q/K/V projections (Q scaled by 0.125*log2e)
    const float QSCALE = 0.125f * 1.4426950408889634f;
    GemmJobs gj;
    gj.j[0] = { gSqh, gSql, gW1h, gW1l, bq, gQh, gQl, QSCALE };
    gj.j[1] = { gSkh, gSkl, gW2h, gW2l, bk, gKh, gKl, 1.0f };
    gj.j[2] = { gSvh, gSvl, gW3h, gW3l, bv, gVh, gVl, 1.0f };
    dim3 gp3(DD / 128, NROW / 128, 3);
    gemm_hmma_qkv<<<gp3, 256, SM_GEMM_BYTES>>>(gj);

    // Fused attention (writes bf16-split O directly)
    dim3 gf(SS / 128, BB * HH);
    fused_attn2<<<gf, 256, FA_SMEM>>>(gQh, gQl, gKh, gKl, gVh, gVl, attn_ptr, gAh, gAl);

    // Output projection
    dim3 gp(DD / 128, NROW / 128);
    gemm_hmma_out<<<gp, 256, SM_GEMM_BYTES>>>(gAh, gAl, gW4h, gW4l, bo, out_ptr);
}

// round 15
// speedup vs baseline: 1.0658x; 1.0394x over previous
#include <cuda_runtime.h>
#include <cuda_bf16.h>
#include <math.h>
#include <stdint.h>

#define BB 2
#define SS 2048
#define DD 1024
#define HH 16
#define DH 64
#define NROW (BB*SS)
#define OUT_ELEMS ((size_t)BB*SS*DD)

// Scratch (device globals)
__device__ __nv_bfloat16 g_Ah[NROW*DD];
__device__ __nv_bfloat16 g_Al[NROW*DD];
__device__ __nv_bfloat16 g_Sqh[NROW*DD], g_Sql[NROW*DD];
__device__ __nv_bfloat16 g_Skh[NROW*DD], g_Skl[NROW*DD];
__device__ __nv_bfloat16 g_Svh[NROW*DD], g_Svl[NROW*DD];
__device__ __nv_bfloat16 g_W1h[DD*DD], g_W1l[DD*DD];
__device__ __nv_bfloat16 g_W2h[DD*DD], g_W2l[DD*DD];
__device__ __nv_bfloat16 g_W3h[DD*DD], g_W3l[DD*DD];
__device__ __nv_bfloat16 g_W4h[DD*DD], g_W4l[DD*DD];
__device__ __nv_bfloat16 g_Qh[NROW*DD], g_Ql[NROW*DD];
__device__ __nv_bfloat16 g_Kh[NROW*DD], g_Kl[NROW*DD];
__device__ __nv_bfloat16 g_Vh[NROW*DD], g_Vl[NROW*DD];

// ===========================================================================
// helpers
// ===========================================================================
__device__ __forceinline__ float fast_exp2(float x) {
    float r;
    asm("ex2.approx.f32 %0, %1;" : "=f"(r) : "f"(x));
    return r;
}
__device__ __forceinline__ uint32_t smem_u32(const void* p) {
    uint32_t a;
    asm("{ .reg .u64 t; cvta.to.shared.u64 t, %1; cvt.u32.u64 %0, t; }"
        : "=r"(a) : "l"(p));
    return a;
}
__device__ __forceinline__ uint32_t sw128(uint32_t off) {
    return off ^ ((off >> 3) & 0x70);
}
__device__ __forceinline__ void cp16(uint32_t dst, const void* src) {
    asm volatile("cp.async.cg.shared.global [%0], [%1], 16;"
                 :: "r"(dst), "l"(src));
}
__device__ __forceinline__ void cp_commit() {
    asm volatile("cp.async.commit_group;" ::: "memory");
}
__device__ __forceinline__ void ldsm_x4(uint32_t& r0, uint32_t& r1,
                                        uint32_t& r2, uint32_t& r3, uint32_t a) {
    asm volatile("ldmatrix.sync.aligned.m8n8.x4.shared.b16 {%0,%1,%2,%3}, [%4];"
                 : "=r"(r0), "=r"(r1), "=r"(r2), "=r"(r3) : "r"(a));
}
__device__ __forceinline__ void ldsm_x4t(uint32_t& r0, uint32_t& r1,
                                         uint32_t& r2, uint32_t& r3, uint32_t a) {
    asm volatile("ldmatrix.sync.aligned.m8n8.x4.trans.shared.b16 {%0,%1,%2,%3}, [%4];"
                 : "=r"(r0), "=r"(r1), "=r"(r2), "=r"(r3) : "r"(a));
}
__device__ __forceinline__ void mma16816(float* d, const uint32_t* a, const uint32_t* b) {
    asm volatile(
        "mma.sync.aligned.m16n8k16.row.col.f32.bf16.bf16.f32 "
        "{%0,%1,%2,%3}, {%4,%5,%6,%7}, {%8,%9}, {%0,%1,%2,%3};"
        : "+f"(d[0]), "+f"(d[1]), "+f"(d[2]), "+f"(d[3])
        : "r"(a[0]), "r"(a[1]), "r"(a[2]), "r"(a[3]), "r"(b[0]), "r"(b[1]));
}
__device__ __forceinline__ uint32_t pack_bf16x2(float lo, float hi) {
    uint32_t r;
    asm("cvt.rn.bf16x2.f32 %0, %1, %2;" : "=r"(r) : "f"(hi), "f"(lo));
    return r;
}

// ===========================================================================
// batched fp32 -> bf16 hi/lo split (4 float4 per thread)
// ===========================================================================
struct SplitJob { const float4* in; uint2* hi; uint2* lo; int n4; };
struct SplitJobs { SplitJob j[7]; };

__device__ __forceinline__ void do_split(const float4* in, uint2* hi, uint2* lo, int i) {
    float4 v = in[i];
    float f[4] = {v.x, v.y, v.z, v.w};
    uint16_t h[4], l[4];
    #pragma unroll
    for (int j = 0; j < 4; j++) {
        __nv_bfloat16 hb = __float2bfloat16(f[j]);
        __nv_bfloat16 lb = __float2bfloat16(f[j] - __bfloat162float(hb));
        h[j] = __bfloat16_as_ushort(hb);
        l[j] = __bfloat16_as_ushort(lb);
    }
    hi[i] = make_uint2((uint32_t)h[0] | ((uint32_t)h[1] << 16),
                       (uint32_t)h[2] | ((uint32_t)h[3] << 16));
    lo[i] = make_uint2((uint32_t)l[0] | ((uint32_t)l[1] << 16),
                       (uint32_t)l[2] | ((uint32_t)l[3] << 16));
}

__global__ __launch_bounds__(256) void split_batch(SplitJobs jobs) {
    SplitJob jb = jobs.j[blockIdx.y];
    int base = blockIdx.x * 1024 + threadIdx.x;
    #pragma unroll
    for (int it = 0; it < 4; it++) {
        int i = base + it * 256;
        if (i < jb.n4) do_split(jb.in, jb.hi, jb.lo, i);
    }
}

// ===========================================================================
// HMMA bf16-split GEMM — CTA tile 128x64, 2 CTAs/SM, 8 warps (4M x 2N) 32x32
// Stage: Ah 0 / Al 16K / Bh 32K / Bl 40K (48KB), double-buffered (96KB).
// ===========================================================================
#define NTS 16
#define GSTAGE2 49152
#define SM_GEMM_BYTES 98304

struct GemmJob {
    const __nv_bfloat16 *ah, *al, *wh, *wl;
    const float* bias;
    __nv_bfloat16 *ch, *cl;
    float scale;
};
struct GemmJobs { GemmJob j[3]; };

__device__ __forceinline__ void gemm_core(
    const __nv_bfloat16* __restrict__ Agh, const __nv_bfloat16* __restrict__ Agl,
    const __nv_bfloat16* __restrict__ Wgh, const __nv_bfloat16* __restrict__ Wgl,
    const float* __restrict__ bias, float* __restrict__ C,
    __nv_bfloat16* __restrict__ Ch, __nv_bfloat16* __restrict__ Cl,
    float scale, int mode, char* smc)
{
    const uint32_t sb = smem_u32(smc);
    const int t = threadIdx.x;
    const int lane = t & 31;
    const int wid = t >> 5;
    const int wm = wid & 3;        // 4 warps over M (32 rows each)
    const int wn = wid >> 2;       // 2 warps over N (32 cols each)
    const int m0 = blockIdx.y * 128;
    const int n0 = blockIdx.x * 64;

    float acc[2][4][4] = {};

    auto prefetch = [&](int s) {
        const int ksl = s * 64;
        const uint32_t base = sb + (s & 1) * GSTAGE2;
        #pragma unroll
        for (int i = 0; i < 4; i++) {
            int idx = t + i * 256;         // 1024: 128 rows x 8 chunks
            int row = idx >> 3, ck = idx & 7;
            uint32_t so = sw128((uint32_t)(row * 128 + ck * 16));
            size_t g = (size_t)(m0 + row) * DD + ksl + ck * 8;
            cp16(base + so, Agh + g);
            cp16(base + 16384 + so, Agl + g);
        }
        #pragma unroll
        for (int i = 0; i < 2; i++) {
            int idx = t + i * 256;         // 512: 64 k-rows x 8 chunks (64 n)
            int kr = idx >> 3, cn = idx & 7;
            uint32_t so = sw128((uint32_t)(kr * 128 + cn * 16));
            size_t g = (size_t)(ksl + kr) * DD + n0 + cn * 8;
            cp16(base + 32768 + so, Wgh + g);
            cp16(base + 40960 + so, Wgl + g);
        }
        cp_commit();
    };

    prefetch(0);
    prefetch(1);

    for (int s = 0; s < NTS; s++) {
        if (s < NTS - 1) asm volatile("cp.async.wait_group 1;" ::: "memory");
        else             asm volatile("cp.async.wait_group 0;" ::: "memory");
        __syncthreads();

        const uint32_t aB  = sb + (s & 1) * GSTAGE2;
        const uint32_t alB = aB + 16384;
        const uint32_t bhB = aB + 32768;
        const uint32_t blB = aB + 40960;

        const int lg = lane >> 3, l7 = lane & 7;

        #pragma unroll
        for (int ks = 0; ks < 4; ks++) {
            const int kb = ks * 32;
            uint32_t bh[4][2], bl[4][2];
            #pragma unroll
            for (int jj = 0; jj < 2; jj++) {
                int ncol = wn * 32 + jj * 16;
                int krow = ks * 16 + (lg & 1) * 8 + l7;
                uint32_t off = sw128((uint32_t)(krow * 128 + ncol * 2 + (lg >> 1) * 16));
                uint32_t r0, r1, r2, r3;
                ldsm_x4t(r0, r1, r2, r3, bhB + off);
                bh[jj*2+0][0] = r0; bh[jj*2+0][1] = r1;
                bh[jj*2+1][0] = r2; bh[jj*2+1][1] = r3;
                ldsm_x4t(r0, r1, r2, r3, blB + off);
                bl[jj*2+0][0] = r0; bl[jj*2+0][1] = r1;
                bl[jj*2+1][0] = r2; bl[jj*2+1][1] = r3;
            }
            #pragma unroll
            for (int im = 0; im < 2; im++) {
                int arow = wm * 32 + im * 16 + (lg & 1) * 8 + l7;
                uint32_t off = sw128((uint32_t)(arow * 128 + kb + (lg >> 1) * 16));
                uint32_t ah[4], al[4];
                ldsm_x4(ah[0], ah[1], ah[2], ah[3], aB + off);
                ldsm_x4(al[0], al[1], al[2], al[3], alB + off);
                #pragma unroll
                for (int jn = 0; jn < 4; jn++) mma16816(acc[im][jn], ah, bh[jn]);
                #pragma unroll
                for (int jn = 0; jn < 4; jn++) mma16816(acc[im][jn], ah, bl[jn]);
                #pragma unroll
                for (int jn = 0; jn < 4; jn++) mma16816(acc[im][jn], al, bh[jn]);
            }
        }
        __syncthreads();
        if (s + 2 < NTS) prefetch(s + 2);
    }

    #pragma unroll
    for (int im = 0; im < 2; im++) {
        int r0 = m0 + wm * 32 + im * 16 + (lane >> 2);
        #pragma unroll
        for (int jn = 0; jn < 4; jn++) {
            int col = n0 + wn * 32 + jn * 8 + (lane & 3) * 2;
            float b0 = bias[col], b1 = bias[col + 1];
            float v00 = acc[im][jn][0] + b0, v01 = acc[im][jn][1] + b1;
            float v10 = acc[im][jn][2] + b0, v11 = acc[im][jn][3] + b1;
            if (mode == 0) {
                *(float2*)&C[(size_t)r0 * DD + col] = make_float2(v00, v01);
                *(float2*)&C[(size_t)(r0 + 8) * DD + col] = make_float2(v10, v11);
            } else {
                v00 *= scale; v01 *= scale; v10 *= scale; v11 *= scale;
                int h = col >> 6, dd = col & 63;
                int b_ = r0 >> 11, s0 = r0 & 2047;
                int b2 = (r0 + 8) >> 11, s1 = (r0 + 8) & 2047;
                size_t off0 = ((size_t)(b_ * HH + h) * SS + s0) * DH + dd;
                size_t off1 = ((size_t)(b2 * HH + h) * SS + s1) * DH + dd;
                uint32_t p0 = pack_bf16x2(v00, v01);
                uint32_t p1 = pack_bf16x2(v10, v11);
                *(uint32_t*)&Ch[off0] = p0;
                *(uint32_t*)&Ch[off1] = p1;
                uint32_t q0 = pack_bf16x2(v00 - __uint_as_float(p0 << 16),
                                          v01 - __uint_as_float(p0 & 0xffff0000u));
                uint32_t q1 = pack_bf16x2(v10 - __uint_as_float(p1 << 16),
                                          v11 - __uint_as_float(p1 & 0xffff0000u));
                *(uint32_t*)&Cl[off0] = q0;
                *(uint32_t*)&Cl[off1] = q1;
            }
        }
    }
}

__global__ __launch_bounds__(256, 2) void gemm_hmma_qkv(GemmJobs jobs) {
    extern __shared__ char smc[];
    GemmJob jb = jobs.j[blockIdx.z];
    gemm_core(jb.ah, jb.al, jb.wh, jb.wl, jb.bias, nullptr,
              jb.ch, jb.cl, jb.scale, 2, smc);
}

__global__ __launch_bounds__(256, 2) void gemm_hmma_out(
    const __nv_bfloat16* __restrict__ Agh, const __nv_bfloat16* __restrict__ Agl,
    const __nv_bfloat16* __restrict__ Wgh, const __nv_bfloat16* __restrict__ Wgl,
    const float* __restrict__ bias, float* __restrict__ C)
{
    extern __shared__ char smc[];
    gemm_core(Agh, Agl, Wgh, Wgl, bias, C, nullptr, nullptr, 1.0f, 0, smc);
}

// ===========================================================================
// Fused attention (R14 best) — UNCHANGED
// ===========================================================================
#define FA_STAGE 65536     // pass B: Kh 0 / Kl 16K / Vh 32K / Vl 48K
#define FA_SMEM (32768 + 2 * FA_STAGE + 2048)

__global__ __launch_bounds__(256, 1) void fused_attn2(
    const __nv_bfloat16* __restrict__ Qh, const __nv_bfloat16* __restrict__ Ql,
    const __nv_bfloat16* __restrict__ Kh, const __nv_bfloat16* __restrict__ Kl,
    const __nv_bfloat16* __restrict__ Vh, const __nv_bfloat16* __restrict__ Vl,
    float* __restrict__ attn,
    __nv_bfloat16* __restrict__ Oh, __nv_bfloat16* __restrict__ Ol)
{
    extern __shared__ char smc[];
    const uint32_t sb = smem_u32(smc);
    const int t = threadIdx.x, lane = t & 31, wid = t >> 5;
    const int m0 = blockIdx.x * 128, bh = blockIdx.y;
    const int wm = wid & 3, wc = wid >> 2;     // 4 M x 2 C
    const int mrow = wm * 32, ncol = wc * 64;
    const size_t gB = (size_t)bh * SS * DH;

    const uint32_t sQh = sb, sQl = sb + 16384;
    float* zred = (float*)(smc + 32768 + 2 * FA_STAGE);

    const int rBn = (lane & 7) + ((lane & 16) >> 1);
    const int cB  = ((lane & 8) << 1);
    const int rV  = (lane & 7) + (lane & 8);
    const int cV  = (lane >> 4) * 16;
    const int l15 = lane & 15, l16 = lane & 16;

    #pragma unroll
    for (int i = 0; i < 4; i++) {
        int idx = t + i * 256;
        int row = idx >> 3, ck = idx & 7;
        uint32_t so = sw128((uint32_t)(row * 128 + ck * 16));
        size_t g = gB + (size_t)(m0 + row) * DH + ck * 8;
        cp16(sQh + so, Qh + g);
        cp16(sQl + so, Ql + g);
    }

    auto prefKh2 = [&](int it) {
        uint32_t base = sb + 32768 + (uint32_t)(it & 1) * 32768;
        #pragma unroll
        for (int i = 0; i < 8; i++) {
            int idx = t + i * 256;
            int row = idx >> 3, ck = idx & 7;
            uint32_t so = sw128((uint32_t)(row * 128 + ck * 16));
            cp16(base + so, Kh + gB + (size_t)(it * 256 + row) * DH + ck * 8);
        }
        cp_commit();
    };
    auto prefKV = [&](int kt) {
        uint32_t base = sb + 32768 + (uint32_t)(kt & 1) * FA_STAGE;
        #pragma unroll
        for (int i = 0; i < 4; i++) {
            int idx = t + i * 256;
            int row = idx >> 3, ck = idx & 7;
            uint32_t so = sw128((uint32_t)(row * 128 + ck * 16));
            size_t g = gB + (size_t)(kt * 128 + row) * DH + ck * 8;
            cp16(base + so, Kh + g);
            cp16(base + 16384 + so, Kl + g);
            cp16(base + 32768 + so, Vh + g);
            cp16(base + 49152 + so, Vl + g);
        }
        cp_commit();
    };

    prefKh2(0);
    prefKh2(1);

    // Pass A
    float zs[2][2] = {};
    for (int it = 0; it < 8; it++) {
        if (it < 7) asm volatile("cp.async.wait_group 1;" ::: "memory");
        else        asm volatile("cp.async.wait_group 0;" ::: "memory");
        __syncthreads();
        uint32_t kb0 = sb + 32768 + (uint32_t)(it & 1) * 32768;

        #pragma unroll
        for (int half = 0; half < 2; half++) {
            uint32_t kb = kb0 + (uint32_t)half * 16384;
            float acc[2][8][4] = {};
            #pragma unroll
            for (int kg = 0; kg < 4; kg++) {
                uint32_t kf[4][4];
                #pragma unroll
                for (int j = 0; j < 4; j++) {
                    uint32_t offB = sw128((uint32_t)((ncol + j * 16 + rBn) * 128 + kg * 32 + cB));
                    ldsm_x4(kf[j][0], kf[j][1], kf[j][2], kf[j][3], kb + offB);
                }
                #pragma unroll
                for (int im = 0; im < 2; im++) {
                    uint32_t offA = sw128((uint32_t)((mrow + im * 16 + l15) * 128 + kg * 32 + l16));
                    uint32_t ah[4];
                    ldsm_x4(ah[0], ah[1], ah[2], ah[3], sQh + offA);
                    #pragma unroll
                    for (int j = 0; j < 4; j++) {
                        mma16816(acc[im][2*j],   ah, &kf[j][0]);
                        mma16816(acc[im][2*j+1], ah, &kf[j][2]);
                    }
                }
            }
            #pragma unroll
            for (int im = 0; im < 2; im++)
                #pragma unroll
                for (int nt = 0; nt < 8; nt++) {
                    zs[im][0] += fast_exp2(acc[im][nt][0]) + fast_exp2(acc[im][nt][1]);
                    zs[im][1] += fast_exp2(acc[im][nt][2]) + fast_exp2(acc[im][nt][3]);
                }
        }
        __syncthreads();
        if (it + 2 < 8) prefKh2(it + 2);
    }

    #pragma unroll
    for (int im = 0; im < 2; im++) {
        zs[im][0] += __shfl_xor_sync(0xffffffffu, zs[im][0], 1);
        zs[im][0] += __shfl_xor_sync(0xffffffffu, zs[im][0], 2);
        zs[im][1] += __shfl_xor_sync(0xffffffffu, zs[im][1], 1);
        zs[im][1] += __shfl_xor_sync(0xffffffffu, zs[im][1], 2);
    }
    if ((lane & 3) == 0) {
        int r0 = mrow + (lane >> 2);
        zred[wc * 128 + r0]      = zs[0][0];
        zred[wc * 128 + r0 + 8]  = zs[0][1];
        zred[wc * 128 + r0 + 16] = zs[1][0];
        zred[wc * 128 + r0 + 24] = zs[1][1];
    }
    __syncthreads();
    float invZ[2][2];
    {
        int r0 = mrow + (lane >> 2);
        invZ[0][0] = 1.0f / (zred[r0]      + zred[128 + r0]);
        invZ[0][1] = 1.0f / (zred[r0 + 8]  + zred[128 + r0 + 8]);
        invZ[1][0] = 1.0f / (zred[r0 + 16] + zred[128 + r0 + 16]);
        invZ[1][1] = 1.0f / (zred[r0 + 24] + zred[128 + r0 + 24]);
    }
    __syncthreads();

    prefKV(0);
    prefKV(1);

    // Pass B
    float o[2][8][4] = {};

    for (int kt = 0; kt < 16; kt++) {
        if (kt < 15) asm volatile("cp.async.wait_group 1;" ::: "memory");
        else         asm volatile("cp.async.wait_group 0;" ::: "memory");
        __syncthreads();
        uint32_t kb = sb + 32768 + (uint32_t)(kt & 1) * FA_STAGE;

        float acc[2][8][4] = {};
        #pragma unroll
        for (int kg = 0; kg < 4; kg++) {
            uint32_t kfh[4][4], kfl[4][4];
            #pragma unroll
            for (int j = 0; j < 4; j++) {
                uint32_t offB = sw128((uint32_t)((ncol + j * 16 + rBn) * 128 + kg * 32 + cB));
                ldsm_x4(kfh[j][0], kfh[j][1], kfh[j][2], kfh[j][3], kb + offB);
                ldsm_x4(kfl[j][0], kfl[j][1], kfl[j][2], kfl[j][3], kb + 16384 + offB);
            }
            #pragma unroll
            for (int im = 0; im < 2; im++) {
                uint32_t offA = sw128((uint32_t)((mrow + im * 16 + l15) * 128 + kg * 32 + l16));
                uint32_t ah[4], al[4];
                ldsm_x4(ah[0], ah[1], ah[2], ah[3], sQh + offA);
                ldsm_x4(al[0], al[1], al[2], al[3], sQl + offA);
                #pragma unroll
                for (int j = 0; j < 4; j++) {
                    mma16816(acc[im][2*j],   ah, &kfh[j][0]);
                    mma16816(acc[im][2*j+1], ah, &kfh[j][2]);
                }
                #pragma unroll
                for (int j = 0; j < 4; j++) {
                    mma16816(acc[im][2*j],   al, &kfh[j][0]);
                    mma16816(acc[im][2*j+1], al, &kfh[j][2]);
                }
                #pragma unroll
                for (int j = 0; j < 4; j++) {
                    mma16816(acc[im][2*j],   ah, &kfl[j][0]);
                    mma16816(acc[im][2*j+1], ah, &kfl[j][2]);
                }
            }
        }

        #pragma unroll
        for (int im = 0; im < 2; im++) {
            const size_t ar0 = (size_t)bh * SS + m0 + mrow + im * 16 + (lane >> 2);
            #pragma unroll
            for (int nt = 0; nt < 8; nt++) {
                float p0 = fast_exp2(acc[im][nt][0]) * invZ[im][0];
                float p1 = fast_exp2(acc[im][nt][1]) * invZ[im][0];
                float p2 = fast_exp2(acc[im][nt][2]) * invZ[im][1];
                float p3 = fast_exp2(acc[im][nt][3]) * invZ[im][1];
                acc[im][nt][0] = p0; acc[im][nt][1] = p1;
                acc[im][nt][2] = p2; acc[im][nt][3] = p3;
                int col = kt * 128 + ncol + nt * 8 + (lane & 3) * 2;
                *(float2*)&attn[ar0 * SS + col]       = make_float2(p0, p1);
                *(float2*)&attn[(ar0 + 8) * SS + col] = make_float2(p2, p3);
            }
        }

        #pragma unroll
        for (int kg = 0; kg < 4; kg++) {
            uint32_t vfh[4][4], vfl[4][4];
            #pragma unroll
            for (int j = 0; j < 4; j++) {
                uint32_t offV = sw128((uint32_t)((ncol + kg * 16 + rV) * 128 + j * 32 + cV));
                ldsm_x4t(vfh[j][0], vfh[j][1], vfh[j][2], vfh[j][3], kb + 32768 + offV);
                ldsm_x4t(vfl[j][0], vfl[j][1], vfl[j][2], vfl[j][3], kb + 49152 + offV);
            }
            #pragma unroll
            for (int im = 0; im < 2; im++) {
                uint32_t ph[4], pl[4];
                #pragma unroll
                for (int half = 0; half < 2; half++) {
                    float* a4 = acc[im][2 * kg + half];
                    uint32_t h0 = pack_bf16x2(a4[0], a4[1]);
                    uint32_t h1 = pack_bf16x2(a4[2], a4[3]);
                    ph[half*2 + 0] = h0;
                    ph[half*2 + 1] = h1;
                    pl[half*2 + 0] = pack_bf16x2(a4[0] - __uint_as_float(h0 << 16),
                                                 a4[1] - __uint_as_float(h0 & 0xffff0000u));
                    pl[half*2 + 1] = pack_bf16x2(a4[2] - __uint_as_float(h1 << 16),
                                                 a4[3] - __uint_as_float(h1 & 0xffff0000u));
                }
                #pragma unroll
                for (int j = 0; j < 4; j++) {
                    mma16816(o[im][2*j],   ph, &vfh[j][0]);
                    mma16816(o[im][2*j+1], ph, &vfh[j][2]);
                }
                #pragma unroll
                for (int j = 0; j < 4; j++) {
                    mma16816(o[im][2*j],   pl, &vfh[j][0]);
                    mma16816(o[im][2*j+1], pl, &vfh[j][2]);
                }
                #pragma unroll
                for (int j = 0; j < 4; j++) {
                    mma16816(o[im][2*j],   ph, &vfl[j][0]);
                    mma16816(o[im][2*j+1], ph, &vfl[j][2]);
                }
            }
        }
        __syncthreads();
        if (kt + 2 < 16) prefKV(kt + 2);
    }

    // O reduction + epilogue
    __syncthreads();
    float* ored = (float*)(smc + 32768);
    if (wc == 1) {
        #pragma unroll
        for (int im = 0; im < 2; im++)
            #pragma unroll
            for (int nt = 0; nt < 8; nt++) {
                int row = mrow + im * 16 + (lane >> 2);
                int col = nt * 8 + (lane & 3) * 2;
                *(float2*)&ored[row * 64 + col] = make_float2(o[im][nt][0], o[im][nt][1]);
                *(float2*)&ored[(row + 8) * 64 + col] = make_float2(o[im][nt][2], o[im][nt][3]);
            }
    }
    __syncthreads();
    if (wc == 0) {
        const int b = bh >> 4, h = bh & 15;
        #pragma unroll
        for (int im = 0; im < 2; im++)
            #pragma unroll
            for (int nt = 0; nt < 8; nt++) {
                int row = mrow + im * 16 + (lane >> 2);
                int col = nt * 8 + (lane & 3) * 2;
                float2 a0 = *(float2*)&ored[row * 64 + col];
                float2 a1 = *(float2*)&ored[(row + 8) * 64 + col];
                float v0 = o[im][nt][0] + a0.x, v1 = o[im][nt][1] + a0.y;
                float v2 = o[im][nt][2] + a1.x, v3 = o[im][nt][3] + a1.y;
                size_t gr = (size_t)(b * SS + m0 + row);
                int gc = h * 64 + col;
                size_t off0 = gr * DD + gc;
                size_t off1 = (gr + 8) * DD + gc;
                uint32_t p0 = pack_bf16x2(v0, v1);
                uint32_t p1 = pack_bf16x2(v2, v3);
                *(uint32_t*)&Oh[off0] = p0;
                *(uint32_t*)&Oh[off1] = p1;
                uint32_t q0 = pack_bf16x2(v0 - __uint_as_float(p0 << 16),
                                          v1 - __uint_as_float(p0 & 0xffff0000u));
                uint32_t q1 = pack_bf16x2(v2 - __uint_as_float(p1 << 16),
                                          v3 - __uint_as_float(p1 & 0xffff0000u));
                *(uint32_t*)&Ol[off0] = q0;
                *(uint32_t*)&Ol[off1] = q1;
            }
    }
}

// ===========================================================================
extern "C" void kernel_launch(void* const* d_in, const int* in_sizes, int n_in,
                              void* d_out, int out_size)
{
    const float* q  = (const float*)d_in[0];
    const float* k  = (const float*)d_in[1];
    const float* v  = (const float*)d_in[2];
    const float* Wq = (const float*)d_in[4];
    const float* bq = (const float*)d_in[5];
    const float* Wk = (const float*)d_in[6];
    const float* bk = (const float*)d_in[7];
    const float* Wv = (const float*)d_in[8];
    const float* bv = (const float*)d_in[9];
    const float* Wo = (const float*)d_in[10];
    const float* bo = (const float*)d_in[11];

    float* out_ptr  = (float*)d_out;
    float* attn_ptr = (float*)d_out + OUT_ELEMS;

    __nv_bfloat16 *gAh, *gAl;
    __nv_bfloat16 *gSqh, *gSql, *gSkh, *gSkl, *gSvh, *gSvl;
    __nv_bfloat16 *gW1h, *gW1l, *gW2h, *gW2l, *gW3h, *gW3l, *gW4h, *gW4l;
    __nv_bfloat16 *gQh, *gQl, *gKh, *gKl, *gVh, *gVl;
    cudaGetSymbolAddress((void**)&gAh, g_Ah);
    cudaGetSymbolAddress((void**)&gAl, g_Al);
    cudaGetSymbolAddress((void**)&gSqh, g_Sqh); cudaGetSymbolAddress((void**)&gSql, g_Sql);
    cudaGetSymbolAddress((void**)&gSkh, g_Skh); cudaGetSymbolAddress((void**)&gSkl, g_Skl);
    cudaGetSymbolAddress((void**)&gSvh, g_Svh); cudaGetSymbolAddress((void**)&gSvl, g_Svl);
    cudaGetSymbolAddress((void**)&gW1h, g_W1h); cudaGetSymbolAddress((void**)&gW1l, g_W1l);
    cudaGetSymbolAddress((void**)&gW2h, g_W2h); cudaGetSymbolAddress((void**)&gW2l, g_W2l);
    cudaGetSymbolAddress((void**)&gW3h, g_W3h); cudaGetSymbolAddress((void**)&gW3l, g_W3l);
    cudaGetSymbolAddress((void**)&gW4h, g_W4h); cudaGetSymbolAddress((void**)&gW4l, g_W4l);
    cudaGetSymbolAddress((void**)&gQh, g_Qh); cudaGetSymbolAddress((void**)&gQl, g_Ql);
    cudaGetSymbolAddress((void**)&gKh, g_Kh); cudaGetSymbolAddress((void**)&gKl, g_Kl);
    cudaGetSymbolAddress((void**)&gVh, g_Vh); cudaGetSymbolAddress((void**)&gVl, g_Vl);

    cudaFuncSetAttribute(gemm_hmma_qkv, cudaFuncAttributeMaxDynamicSharedMemorySize,
                         SM_GEMM_BYTES);
    cudaFuncSetAttribute(gemm_hmma_out, cudaFuncAttributeMaxDynamicSharedMemorySize,
                         SM_GEMM_BYTES);
    cudaFuncSetAttribute(fused_attn2, cudaFuncAttributeMaxDynamicSharedMemorySize,
                         FA_SMEM);

    const int NA4 = (int)(OUT_ELEMS / 4);
    const int NW4 = DD * DD / 4;

    SplitJobs jobs;
    jobs.j[0] = { (const float4*)q,  (uint2*)gSqh, (uint2*)gSql, NA4 };
    jobs.j[1] = { (const float4*)k,  (uint2*)gSkh, (uint2*)gSkl, NA4 };
    jobs.j[2] = { (const float4*)v,  (uint2*)gSvh, (uint2*)gSvl, NA4 };
    jobs.j[3] = { (const float4*)Wq, (uint2*)gW1h, (uint2*)gW1l, NW4 };
    jobs.j[4] = { (const float4*)Wk, (uint2*)gW2h, (uint2*)gW2l, NW4 };
    jobs.j[5] = { (const float4*)Wv, (uint2*)gW3h, (uint2*)gW3l, NW4 };
    jobs.j[6] = { (const float4*)Wo, (uint2*)gW4h, (uint2*)gW4l, NW4 };
    split_batch<<<dim3((NA4 + 1023) / 1024, 7), 256>>>(jobs);

    const float QSCALE = 0.125f * 1.4426950408889634f;
    GemmJobs gj;
    gj.j[0] = { gSqh, gSql, gW1h, gW1l, bq, gQh, gQl, QSCALE };
    gj.j[1] = { gSkh, gSkl, gW2h, gW2l, bk, gKh, gKl, 1.0f };
    gj.j[2] = { gSvh, gSvl, gW3h, gW3l, bv, gVh, gVl, 1.0f };
    dim3 gp3(DD / 64, NROW / 128, 3);   // (16, 32, 3)
    gemm_hmma_qkv<<<gp3, 256, SM_GEMM_BYTES>>>(gj);

    dim3 gf(SS / 128, BB * HH);
    fused_attn2<<<gf, 256, FA_SMEM>>>(gQh, gQl, gKh, gKl, gVh, gVl, attn_ptr, gAh, gAl);

    dim3 gp(DD / 64, NROW / 128);       // (16, 32)
    gemm_hmma_out<<<gp, 256, SM_GEMM_BYTES>>>(gAh, gAl, gW4h, gW4l, bo, out_ptr);
}

// round 16
// speedup vs baseline: 1.1153x; 1.0464x over previous
#include <cuda_runtime.h>
#include <cuda_bf16.h>
#include <math.h>
#include <stdint.h>

#define BB 2
#define SS 2048
#define DD 1024
#define HH 16
#define DH 64
#define NROW (BB*SS)
#define OUT_ELEMS ((size_t)BB*SS*DD)

// Scratch (device globals)
__device__ __nv_bfloat16 g_Ah[NROW*DD];
__device__ __nv_bfloat16 g_Al[NROW*DD];
__device__ __nv_bfloat16 g_Sqh[NROW*DD], g_Sql[NROW*DD];
__device__ __nv_bfloat16 g_Skh[NROW*DD], g_Skl[NROW*DD];
__device__ __nv_bfloat16 g_Svh[NROW*DD], g_Svl[NROW*DD];
__device__ __nv_bfloat16 g_W1h[DD*DD], g_W1l[DD*DD];
__device__ __nv_bfloat16 g_W2h[DD*DD], g_W2l[DD*DD];
__device__ __nv_bfloat16 g_W3h[DD*DD], g_W3l[DD*DD];
__device__ __nv_bfloat16 g_W4h[DD*DD], g_W4l[DD*DD];
__device__ __nv_bfloat16 g_Qh[NROW*DD], g_Ql[NROW*DD];
__device__ __nv_bfloat16 g_Kh[NROW*DD], g_Kl[NROW*DD];
__device__ __nv_bfloat16 g_Vh[NROW*DD], g_Vl[NROW*DD];

// ===========================================================================
// helpers
// ===========================================================================
__device__ __forceinline__ float fast_exp2(float x) {
    float r;
    asm("ex2.approx.f32 %0, %1;" : "=f"(r) : "f"(x));
    return r;
}
__device__ __forceinline__ uint32_t smem_u32(const void* p) {
    uint32_t a;
    asm("{ .reg .u64 t; cvta.to.shared.u64 t, %1; cvt.u32.u64 %0, t; }"
        : "=r"(a) : "l"(p));
    return a;
}
__device__ __forceinline__ uint32_t sw128(uint32_t off) {
    return off ^ ((off >> 3) & 0x70);
}
__device__ __forceinline__ void cp16(uint32_t dst, const void* src) {
    asm volatile("cp.async.cg.shared.global [%0], [%1], 16;"
                 :: "r"(dst), "l"(src));
}
__device__ __forceinline__ void cp_commit() {
    asm volatile("cp.async.commit_group;" ::: "memory");
}
__device__ __forceinline__ void ldsm_x4(uint32_t& r0, uint32_t& r1,
                                        uint32_t& r2, uint32_t& r3, uint32_t a) {
    asm volatile("ldmatrix.sync.aligned.m8n8.x4.shared.b16 {%0,%1,%2,%3}, [%4];"
                 : "=r"(r0), "=r"(r1), "=r"(r2), "=r"(r3) : "r"(a));
}
__device__ __forceinline__ void ldsm_x4t(uint32_t& r0, uint32_t& r1,
                                         uint32_t& r2, uint32_t& r3, uint32_t a) {
    asm volatile("ldmatrix.sync.aligned.m8n8.x4.trans.shared.b16 {%0,%1,%2,%3}, [%4];"
                 : "=r"(r0), "=r"(r1), "=r"(r2), "=r"(r3) : "r"(a));
}
__device__ __forceinline__ void mma16816(float* d, const uint32_t* a, const uint32_t* b) {
    asm volatile(
        "mma.sync.aligned.m16n8k16.row.col.f32.bf16.bf16.f32 "
        "{%0,%1,%2,%3}, {%4,%5,%6,%7}, {%8,%9}, {%0,%1,%2,%3};"
        : "+f"(d[0]), "+f"(d[1]), "+f"(d[2]), "+f"(d[3])
        : "r"(a[0]), "r"(a[1]), "r"(a[2]), "r"(a[3]), "r"(b[0]), "r"(b[1]));
}
__device__ __forceinline__ uint32_t pack_bf16x2(float lo, float hi) {
    uint32_t r;
    asm("cvt.rn.bf16x2.f32 %0, %1, %2;" : "=r"(r) : "f"(hi), "f"(lo));
    return r;
}

// ===========================================================================
// batched fp32 -> bf16 hi/lo split (4 float4 per thread)
// ===========================================================================
struct SplitJob { const float4* in; uint2* hi; uint2* lo; int n4; };
struct SplitJobs { SplitJob j[7]; };

__device__ __forceinline__ void do_split(const float4* in, uint2* hi, uint2* lo, int i) {
    float4 v = in[i];
    float f[4] = {v.x, v.y, v.z, v.w};
    uint16_t h[4], l[4];
    #pragma unroll
    for (int j = 0; j < 4; j++) {
        __nv_bfloat16 hb = __float2bfloat16(f[j]);
        __nv_bfloat16 lb = __float2bfloat16(f[j] - __bfloat162float(hb));
        h[j] = __bfloat16_as_ushort(hb);
        l[j] = __bfloat16_as_ushort(lb);
    }
    hi[i] = make_uint2((uint32_t)h[0] | ((uint32_t)h[1] << 16),
                       (uint32_t)h[2] | ((uint32_t)h[3] << 16));
    lo[i] = make_uint2((uint32_t)l[0] | ((uint32_t)l[1] << 16),
                       (uint32_t)l[2] | ((uint32_t)l[3] << 16));
}

__global__ __launch_bounds__(256) void split_batch(SplitJobs jobs) {
    SplitJob jb = jobs.j[blockIdx.y];
    int base = blockIdx.x * 1024 + threadIdx.x;
    #pragma unroll
    for (int it = 0; it < 4; it++) {
        int i = base + it * 256;
        if (i < jb.n4) do_split(jb.in, jb.hi, jb.lo, i);
    }
}

// ===========================================================================
// HMMA bf16-split GEMM — CTA 128x64, 2 CTAs/SM (R15 proven, unchanged)
// ===========================================================================
#define NTS 16
#define GSTAGE2 49152
#define SM_GEMM_BYTES 98304

struct GemmJob {
    const __nv_bfloat16 *ah, *al, *wh, *wl;
    const float* bias;
    __nv_bfloat16 *ch, *cl;
    float scale;
};
struct GemmJobs { GemmJob j[3]; };

__device__ __forceinline__ void gemm_core(
    const __nv_bfloat16* __restrict__ Agh, const __nv_bfloat16* __restrict__ Agl,
    const __nv_bfloat16* __restrict__ Wgh, const __nv_bfloat16* __restrict__ Wgl,
    const float* __restrict__ bias, float* __restrict__ C,
    __nv_bfloat16* __restrict__ Ch, __nv_bfloat16* __restrict__ Cl,
    float scale, int mode, char* smc)
{
    const uint32_t sb = smem_u32(smc);
    const int t = threadIdx.x;
    const int lane = t & 31;
    const int wid = t >> 5;
    const int wm = wid & 3;
    const int wn = wid >> 2;
    const int m0 = blockIdx.y * 128;
    const int n0 = blockIdx.x * 64;

    float acc[2][4][4] = {};

    auto prefetch = [&](int s) {
        const int ksl = s * 64;
        const uint32_t base = sb + (s & 1) * GSTAGE2;
        #pragma unroll
        for (int i = 0; i < 4; i++) {
            int idx = t + i * 256;
            int row = idx >> 3, ck = idx & 7;
            uint32_t so = sw128((uint32_t)(row * 128 + ck * 16));
            size_t g = (size_t)(m0 + row) * DD + ksl + ck * 8;
            cp16(base + so, Agh + g);
            cp16(base + 16384 + so, Agl + g);
        }
        #pragma unroll
        for (int i = 0; i < 2; i++) {
            int idx = t + i * 256;
            int kr = idx >> 3, cn = idx & 7;
            uint32_t so = sw128((uint32_t)(kr * 128 + cn * 16));
            size_t g = (size_t)(ksl + kr) * DD + n0 + cn * 8;
            cp16(base + 32768 + so, Wgh + g);
            cp16(base + 40960 + so, Wgl + g);
        }
        cp_commit();
    };

    prefetch(0);
    prefetch(1);

    for (int s = 0; s < NTS; s++) {
        if (s < NTS - 1) asm volatile("cp.async.wait_group 1;" ::: "memory");
        else             asm volatile("cp.async.wait_group 0;" ::: "memory");
        __syncthreads();

        const uint32_t aB  = sb + (s & 1) * GSTAGE2;
        const uint32_t alB = aB + 16384;
        const uint32_t bhB = aB + 32768;
        const uint32_t blB = aB + 40960;

        const int lg = lane >> 3, l7 = lane & 7;

        #pragma unroll
        for (int ks = 0; ks < 4; ks++) {
            const int kb = ks * 32;
            uint32_t bh[4][2], bl[4][2];
            #pragma unroll
            for (int jj = 0; jj < 2; jj++) {
                int ncol = wn * 32 + jj * 16;
                int krow = ks * 16 + (lg & 1) * 8 + l7;
                uint32_t off = sw128((uint32_t)(krow * 128 + ncol * 2 + (lg >> 1) * 16));
                uint32_t r0, r1, r2, r3;
                ldsm_x4t(r0, r1, r2, r3, bhB + off);
                bh[jj*2+0][0] = r0; bh[jj*2+0][1] = r1;
                bh[jj*2+1][0] = r2; bh[jj*2+1][1] = r3;
                ldsm_x4t(r0, r1, r2, r3, blB + off);
                bl[jj*2+0][0] = r0; bl[jj*2+0][1] = r1;
                bl[jj*2+1][0] = r2; bl[jj*2+1][1] = r3;
            }
            #pragma unroll
            for (int im = 0; im < 2; im++) {
                int arow = wm * 32 + im * 16 + (lg & 1) * 8 + l7;
                uint32_t off = sw128((uint32_t)(arow * 128 + kb + (lg >> 1) * 16));
                uint32_t ah[4], al[4];
                ldsm_x4(ah[0], ah[1], ah[2], ah[3], aB + off);
                ldsm_x4(al[0], al[1], al[2], al[3], alB + off);
                #pragma unroll
                for (int jn = 0; jn < 4; jn++) mma16816(acc[im][jn], ah, bh[jn]);
                #pragma unroll
                for (int jn = 0; jn < 4; jn++) mma16816(acc[im][jn], ah, bl[jn]);
                #pragma unroll
                for (int jn = 0; jn < 4; jn++) mma16816(acc[im][jn], al, bh[jn]);
            }
        }
        __syncthreads();
        if (s + 2 < NTS) prefetch(s + 2);
    }

    #pragma unroll
    for (int im = 0; im < 2; im++) {
        int r0 = m0 + wm * 32 + im * 16 + (lane >> 2);
        #pragma unroll
        for (int jn = 0; jn < 4; jn++) {
            int col = n0 + wn * 32 + jn * 8 + (lane & 3) * 2;
            float b0 = bias[col], b1 = bias[col + 1];
            float v00 = acc[im][jn][0] + b0, v01 = acc[im][jn][1] + b1;
            float v10 = acc[im][jn][2] + b0, v11 = acc[im][jn][3] + b1;
            if (mode == 0) {
                *(float2*)&C[(size_t)r0 * DD + col] = make_float2(v00, v01);
                *(float2*)&C[(size_t)(r0 + 8) * DD + col] = make_float2(v10, v11);
            } else {
                v00 *= scale; v01 *= scale; v10 *= scale; v11 *= scale;
                int h = col >> 6, dd = col & 63;
                int b_ = r0 >> 11, s0 = r0 & 2047;
                int b2 = (r0 + 8) >> 11, s1 = (r0 + 8) & 2047;
                size_t off0 = ((size_t)(b_ * HH + h) * SS + s0) * DH + dd;
                size_t off1 = ((size_t)(b2 * HH + h) * SS + s1) * DH + dd;
                uint32_t p0 = pack_bf16x2(v00, v01);
                uint32_t p1 = pack_bf16x2(v10, v11);
                *(uint32_t*)&Ch[off0] = p0;
                *(uint32_t*)&Ch[off1] = p1;
                uint32_t q0 = pack_bf16x2(v00 - __uint_as_float(p0 << 16),
                                          v01 - __uint_as_float(p0 & 0xffff0000u));
                uint32_t q1 = pack_bf16x2(v10 - __uint_as_float(p1 << 16),
                                          v11 - __uint_as_float(p1 & 0xffff0000u));
                *(uint32_t*)&Cl[off0] = q0;
                *(uint32_t*)&Cl[off1] = q1;
            }
        }
    }
}

__global__ __launch_bounds__(256, 2) void gemm_hmma_qkv(GemmJobs jobs) {
    extern __shared__ char smc[];
    GemmJob jb = jobs.j[blockIdx.z];
    gemm_core(jb.ah, jb.al, jb.wh, jb.wl, jb.bias, nullptr,
              jb.ch, jb.cl, jb.scale, 2, smc);
}

__global__ __launch_bounds__(256, 2) void gemm_hmma_out(
    const __nv_bfloat16* __restrict__ Agh, const __nv_bfloat16* __restrict__ Agl,
    const __nv_bfloat16* __restrict__ Wgh, const __nv_bfloat16* __restrict__ Wgl,
    const float* __restrict__ bias, float* __restrict__ C)
{
    extern __shared__ char smc[];
    gemm_core(Agh, Agl, Wgh, Wgl, bias, C, nullptr, nullptr, 1.0f, 0, smc);
}

// ===========================================================================
// Fused attention v8: CTA = 64 q-rows (grid 1024 -> 98.7% wave util).
// Warps 2M x 4C (warp = 32 rows x 32 cols). Q 16K; pass A stages 2x32K;
// pass B stages 2x64K; zred 1K; ored (48K) reuses stage area.
// ===========================================================================
#define FA_Q 16384
#define FA_STAGE 65536
#define FA_ZRED (FA_Q + 2 * FA_STAGE)            // 147456
#define FA_SMEM (FA_ZRED + 1024)                 // 148480

__global__ __launch_bounds__(256, 1) void fused_attn2(
    const __nv_bfloat16* __restrict__ Qh, const __nv_bfloat16* __restrict__ Ql,
    const __nv_bfloat16* __restrict__ Kh, const __nv_bfloat16* __restrict__ Kl,
    const __nv_bfloat16* __restrict__ Vh, const __nv_bfloat16* __restrict__ Vl,
    float* __restrict__ attn,
    __nv_bfloat16* __restrict__ Oh, __nv_bfloat16* __restrict__ Ol)
{
    extern __shared__ char smc[];
    const uint32_t sb = smem_u32(smc);
    const int t = threadIdx.x, lane = t & 31, wid = t >> 5;
    const int m0 = blockIdx.x * 64, bh = blockIdx.y;
    const int wm = wid & 1, wc = wid >> 1;       // 2 M x 4 C
    const int mrow = wm * 32, ncol = wc * 32;
    const size_t gB = (size_t)bh * SS * DH;

    const uint32_t sQh = sb, sQl = sb + 8192;
    float* zred = (float*)(smc + FA_ZRED);       // [4][64]

    const int rBn = (lane & 7) + ((lane & 16) >> 1);
    const int cB  = ((lane & 8) << 1);
    const int rV  = (lane & 7) + (lane & 8);
    const int cV  = (lane >> 4) * 16;
    const int l15 = lane & 15, l16 = lane & 16;

    // Q loads: 64 rows x 8 chunks, h + l
    #pragma unroll
    for (int i = 0; i < 2; i++) {
        int idx = t + i * 256;
        int row = idx >> 3, ck = idx & 7;
        uint32_t so = sw128((uint32_t)(row * 128 + ck * 16));
        size_t g = gB + (size_t)(m0 + row) * DH + ck * 8;
        cp16(sQh + so, Qh + g);
        cp16(sQl + so, Ql + g);
    }

    auto prefKh2 = [&](int it) {   // pass A: 256 K rows of Kh (32KB)
        uint32_t base = sb + FA_Q + (uint32_t)(it & 1) * 32768;
        #pragma unroll
        for (int i = 0; i < 8; i++) {
            int idx = t + i * 256;
            int row = idx >> 3, ck = idx & 7;
            uint32_t so = sw128((uint32_t)(row * 128 + ck * 16));
            cp16(base + so, Kh + gB + (size_t)(it * 256 + row) * DH + ck * 8);
        }
        cp_commit();
    };
    auto prefKV = [&](int kt) {    // pass B: 128 rows Kh/Kl/Vh/Vl (64KB)
        uint32_t base = sb + FA_Q + (uint32_t)(kt & 1) * FA_STAGE;
        #pragma unroll
        for (int i = 0; i < 4; i++) {
            int idx = t + i * 256;
            int row = idx >> 3, ck = idx & 7;
            uint32_t so = sw128((uint32_t)(row * 128 + ck * 16));
            size_t g = gB + (size_t)(kt * 128 + row) * DH + ck * 8;
            cp16(base + so, Kh + g);
            cp16(base + 16384 + so, Kl + g);
            cp16(base + 32768 + so, Vh + g);
            cp16(base + 49152 + so, Vl + g);
        }
        cp_commit();
    };

    prefKh2(0);
    prefKh2(1);

    // ------------------- Pass A: Z sums -------------------
    float zs[2][2] = {};
    for (int it = 0; it < 8; it++) {
        if (it < 7) asm volatile("cp.async.wait_group 1;" ::: "memory");
        else        asm volatile("cp.async.wait_group 0;" ::: "memory");
        __syncthreads();
        uint32_t kb0 = sb + FA_Q + (uint32_t)(it & 1) * 32768;

        #pragma unroll
        for (int half = 0; half < 2; half++) {
            uint32_t kb = kb0 + (uint32_t)half * 16384;
            float acc[2][4][4] = {};
            #pragma unroll
            for (int kg = 0; kg < 4; kg++) {
                uint32_t kf[2][4];
                #pragma unroll
                for (int j = 0; j < 2; j++) {
                    uint32_t offB = sw128((uint32_t)((ncol + j * 16 + rBn) * 128 + kg * 32 + cB));
                    ldsm_x4(kf[j][0], kf[j][1], kf[j][2], kf[j][3], kb + offB);
                }
                #pragma unroll
                for (int im = 0; im < 2; im++) {
                    uint32_t offA = sw128((uint32_t)((mrow + im * 16 + l15) * 128 + kg * 32 + l16));
                    uint32_t ah[4];
                    ldsm_x4(ah[0], ah[1], ah[2], ah[3], sQh + offA);
                    #pragma unroll
                    for (int j = 0; j < 2; j++) {
                        mma16816(acc[im][2*j],   ah, &kf[j][0]);
                        mma16816(acc[im][2*j+1], ah, &kf[j][2]);
                    }
                }
            }
            #pragma unroll
            for (int im = 0; im < 2; im++)
                #pragma unroll
                for (int nt = 0; nt < 4; nt++) {
                    zs[im][0] += fast_exp2(acc[im][nt][0]) + fast_exp2(acc[im][nt][1]);
                    zs[im][1] += fast_exp2(acc[im][nt][2]) + fast_exp2(acc[im][nt][3]);
                }
        }
        __syncthreads();
        if (it + 2 < 8) prefKh2(it + 2);
    }

    #pragma unroll
    for (int im = 0; im < 2; im++) {
        zs[im][0] += __shfl_xor_sync(0xffffffffu, zs[im][0], 1);
        zs[im][0] += __shfl_xor_sync(0xffffffffu, zs[im][0], 2);
        zs[im][1] += __shfl_xor_sync(0xffffffffu, zs[im][1], 1);
        zs[im][1] += __shfl_xor_sync(0xffffffffu, zs[im][1], 2);
    }
    if ((lane & 3) == 0) {
        #pragma unroll
        for (int im = 0; im < 2; im++) {
            int r = mrow + im * 16 + (lane >> 2);
            zred[wc * 64 + r]     = zs[im][0];
            zred[wc * 64 + r + 8] = zs[im][1];
        }
    }
    __syncthreads();
    float invZ[2][2];
    #pragma unroll
    for (int im = 0; im < 2; im++) {
        int r = mrow + im * 16 + (lane >> 2);
        invZ[im][0] = 1.0f / (zred[r] + zred[64 + r] + zred[128 + r] + zred[192 + r]);
        invZ[im][1] = 1.0f / (zred[r + 8] + zred[64 + r + 8] + zred[128 + r + 8] + zred[192 + r + 8]);
    }
    __syncthreads();

    prefKV(0);
    prefKV(1);

    // ------------------- Pass B -------------------
    float o[2][8][4] = {};

    for (int kt = 0; kt < 16; kt++) {
        if (kt < 15) asm volatile("cp.async.wait_group 1;" ::: "memory");
        else         asm volatile("cp.async.wait_group 0;" ::: "memory");
        __syncthreads();
        uint32_t kb = sb + FA_Q + (uint32_t)(kt & 1) * FA_STAGE;

        float acc[2][4][4] = {};
        #pragma unroll
        for (int kg = 0; kg < 4; kg++) {
            uint32_t kfh[2][4], kfl[2][4];
            #pragma unroll
            for (int j = 0; j < 2; j++) {
                uint32_t offB = sw128((uint32_t)((ncol + j * 16 + rBn) * 128 + kg * 32 + cB));
                ldsm_x4(kfh[j][0], kfh[j][1], kfh[j][2], kfh[j][3], kb + offB);
                ldsm_x4(kfl[j][0], kfl[j][1], kfl[j][2], kfl[j][3], kb + 16384 + offB);
            }
            #pragma unroll
            for (int im = 0; im < 2; im++) {
                uint32_t offA = sw128((uint32_t)((mrow + im * 16 + l15) * 128 + kg * 32 + l16));
                uint32_t ah[4], al[4];
                ldsm_x4(ah[0], ah[1], ah[2], ah[3], sQh + offA);
                ldsm_x4(al[0], al[1], al[2], al[3], sQl + offA);
                #pragma unroll
                for (int j = 0; j < 2; j++) {
                    mma16816(acc[im][2*j],   ah, &kfh[j][0]);
                    mma16816(acc[im][2*j+1], ah, &kfh[j][2]);
                }
                #pragma unroll
                for (int j = 0; j < 2; j++) {
                    mma16816(acc[im][2*j],   al, &kfh[j][0]);
                    mma16816(acc[im][2*j+1], al, &kfh[j][2]);
                }
                #pragma unroll
                for (int j = 0; j < 2; j++) {
                    mma16816(acc[im][2*j],   ah, &kfl[j][0]);
                    mma16816(acc[im][2*j+1], ah, &kfl[j][2]);
                }
            }
        }

        // exp + attn store (warp: 32 rows x 32 cols)
        #pragma unroll
        for (int im = 0; im < 2; im++) {
            const size_t ar0 = (size_t)bh * SS + m0 + mrow + im * 16 + (lane >> 2);
            #pragma unroll
            for (int nt = 0; nt < 4; nt++) {
                float p0 = fast_exp2(acc[im][nt][0]) * invZ[im][0];
                float p1 = fast_exp2(acc[im][nt][1]) * invZ[im][0];
                float p2 = fast_exp2(acc[im][nt][2]) * invZ[im][1];
                float p3 = fast_exp2(acc[im][nt][3]) * invZ[im][1];
                acc[im][nt][0] = p0; acc[im][nt][1] = p1;
                acc[im][nt][2] = p2; acc[im][nt][3] = p3;
                int col = kt * 128 + ncol + nt * 8 + (lane & 3) * 2;
                *(float2*)&attn[ar0 * SS + col]       = make_float2(p0, p1);
                *(float2*)&attn[(ar0 + 8) * SS + col] = make_float2(p2, p3);
            }
        }

        // PV: warp's k-slice = its 32 S-cols (2 k16 chunks)
        #pragma unroll
        for (int kg = 0; kg < 2; kg++) {
            uint32_t vfh[4][4], vfl[4][4];
            #pragma unroll
            for (int j = 0; j < 4; j++) {
                uint32_t offV = sw128((uint32_t)((ncol + kg * 16 + rV) * 128 + j * 32 + cV));
                ldsm_x4t(vfh[j][0], vfh[j][1], vfh[j][2], vfh[j][3], kb + 32768 + offV);
                ldsm_x4t(vfl[j][0], vfl[j][1], vfl[j][2], vfl[j][3], kb + 49152 + offV);
            }
            #pragma unroll
            for (int im = 0; im < 2; im++) {
                uint32_t ph[4], pl[4];
                #pragma unroll
                for (int half = 0; half < 2; half++) {
                    float* a4 = acc[im][2 * kg + half];
                    uint32_t h0 = pack_bf16x2(a4[0], a4[1]);
                    uint32_t h1 = pack_bf16x2(a4[2], a4[3]);
                    ph[half*2 + 0] = h0;
                    ph[half*2 + 1] = h1;
                    pl[half*2 + 0] = pack_bf16x2(a4[0] - __uint_as_float(h0 << 16),
                                                 a4[1] - __uint_as_float(h0 & 0xffff0000u));
                    pl[half*2 + 1] = pack_bf16x2(a4[2] - __uint_as_float(h1 << 16),
                                                 a4[3] - __uint_as_float(h1 & 0xffff0000u));
                }
                #pragma unroll
                for (int j = 0; j < 4; j++) {
                    mma16816(o[im][2*j],   ph, &vfh[j][0]);
                    mma16816(o[im][2*j+1], ph, &vfh[j][2]);
                }
                #pragma unroll
                for (int j = 0; j < 4; j++) {
                    mma16816(o[im][2*j],   pl, &vfh[j][0]);
                    mma16816(o[im][2*j+1], pl, &vfh[j][2]);
                }
                #pragma unroll
                for (int j = 0; j < 4; j++) {
                    mma16816(o[im][2*j],   ph, &vfl[j][0]);
                    mma16816(o[im][2*j+1], ph, &vfl[j][2]);
                }
            }
        }
        __syncthreads();
        if (kt + 2 < 16) prefKV(kt + 2);
    }

    // ------------------- O reduction (4 col-warps) + epilogue -------------------
    __syncthreads();
    float* ored = (float*)(smc + FA_Q);   // [3][64][64] partials
    if (wc > 0) {
        float* dst = ored + (size_t)(wc - 1) * 4096;
        #pragma unroll
        for (int im = 0; im < 2; im++)
            #pragma unroll
            for (int nt = 0; nt < 8; nt++) {
                int row = mrow + im * 16 + (lane >> 2);
                int col = nt * 8 + (lane & 3) * 2;
                *(float2*)&dst[row * 64 + col] = make_float2(o[im][nt][0], o[im][nt][1]);
                *(float2*)&dst[(row + 8) * 64 + col] = make_float2(o[im][nt][2], o[im][nt][3]);
            }
    }
    __syncthreads();
    if (wc == 0) {
        const int b = bh >> 4, h = bh & 15;
        #pragma unroll
        for (int im = 0; im < 2; im++)
            #pragma unroll
            for (int nt = 0; nt < 8; nt++) {
                int row = mrow + im * 16 + (lane >> 2);
                int col = nt * 8 + (lane & 3) * 2;
                float2 a0 = *(float2*)&ored[row * 64 + col];
                float2 b0 = *(float2*)&ored[4096 + row * 64 + col];
                float2 c0 = *(float2*)&ored[8192 + row * 64 + col];
                float2 a1 = *(float2*)&ored[(row + 8) * 64 + col];
                float2 b1 = *(float2*)&ored[4096 + (row + 8) * 64 + col];
                float2 c1 = *(float2*)&ored[8192 + (row + 8) * 64 + col];
                float v0 = o[im][nt][0] + a0.x + b0.x + c0.x;
                float v1 = o[im][nt][1] + a0.y + b0.y + c0.y;
                float v2 = o[im][nt][2] + a1.x + b1.x + c1.x;
                float v3 = o[im][nt][3] + a1.y + b1.y + c1.y;
                size_t gr = (size_t)(b * SS + m0 + row);
                int gc = h * 64 + col;
                size_t off0 = gr * DD + gc;
                size_t off1 = (gr + 8) * DD + gc;
                uint32_t p0 = pack_bf16x2(v0, v1);
                uint32_t p1 = pack_bf16x2(v2, v3);
                *(uint32_t*)&Oh[off0] = p0;
                *(uint32_t*)&Oh[off1] = p1;
                uint32_t q0 = pack_bf16x2(v0 - __uint_as_float(p0 << 16),
                                          v1 - __uint_as_float(p0 & 0xffff0000u));
                uint32_t q1 = pack_bf16x2(v2 - __uint_as_float(p1 << 16),
                                          v3 - __uint_as_float(p1 & 0xffff0000u));
                *(uint32_t*)&Ol[off0] = q0;
                *(uint32_t*)&Ol[off1] = q1;
            }
    }
}

// ===========================================================================
extern "C" void kernel_launch(void* const* d_in, const int* in_sizes, int n_in,
                              void* d_out, int out_size)
{
    const float* q  = (const float*)d_in[0];
    const float* k  = (const float*)d_in[1];
    const float* v  = (const float*)d_in[2];
    const float* Wq = (const float*)d_in[4];
    const float* bq = (const float*)d_in[5];
    const float* Wk = (const float*)d_in[6];
    const float* bk = (const float*)d_in[7];
    const float* Wv = (const float*)d_in[8];
    const float* bv = (const float*)d_in[9];
    const float* Wo = (const float*)d_in[10];
    const float* bo = (const float*)d_in[11];

    float* out_ptr  = (float*)d_out;
    float* attn_ptr = (float*)d_out + OUT_ELEMS;

    __nv_bfloat16 *gAh, *gAl;
    __nv_bfloat16 *gSqh, *gSql, *gSkh, *gSkl, *gSvh, *gSvl;
    __nv_bfloat16 *gW1h, *gW1l, *gW2h, *gW2l, *gW3h, *gW3l, *gW4h, *gW4l;
    __nv_bfloat16 *gQh, *gQl, *gKh, *gKl, *gVh, *gVl;
    cudaGetSymbolAddress((void**)&gAh, g_Ah);
    cudaGetSymbolAddress((void**)&gAl, g_Al);
    cudaGetSymbolAddress((void**)&gSqh, g_Sqh); cudaGetSymbolAddress((void**)&gSql, g_Sql);
    cudaGetSymbolAddress((void**)&gSkh, g_Skh); cudaGetSymbolAddress((void**)&gSkl, g_Skl);
    cudaGetSymbolAddress((void**)&gSvh, g_Svh); cudaGetSymbolAddress((void**)&gSvl, g_Svl);
    cudaGetSymbolAddress((void**)&gW1h, g_W1h); cudaGetSymbolAddress((void**)&gW1l, g_W1l);
    cudaGetSymbolAddress((void**)&gW2h, g_W2h); cudaGetSymbolAddress((void**)&gW2l, g_W2l);
    cudaGetSymbolAddress((void**)&gW3h, g_W3h); cudaGetSymbolAddress((void**)&gW3l, g_W3l);
    cudaGetSymbolAddress((void**)&gW4h, g_W4h); cudaGetSymbolAddress((void**)&gW4l, g_W4l);
    cudaGetSymbolAddress((void**)&gQh, g_Qh); cudaGetSymbolAddress((void**)&gQl, g_Ql);
    cudaGetSymbolAddress((void**)&gKh, g_Kh); cudaGetSymbolAddress((void**)&gKl, g_Kl);
    cudaGetSymbolAddress((void**)&gVh, g_Vh); cudaGetSymbolAddress((void**)&gVl, g_Vl);

    cudaFuncSetAttribute(gemm_hmma_qkv, cudaFuncAttributeMaxDynamicSharedMemorySize,
                         SM_GEMM_BYTES);
    cudaFuncSetAttribute(gemm_hmma_out, cudaFuncAttributeMaxDynamicSharedMemorySize,
                         SM_GEMM_BYTES);
    cudaFuncSetAttribute(fused_attn2, cudaFuncAttributeMaxDynamicSharedMemorySize,
                         FA_SMEM);

    const int NA4 = (int)(OUT_ELEMS / 4);
    const int NW4 = DD * DD / 4;

    SplitJobs jobs;
    jobs.j[0] = { (const float4*)q,  (uint2*)gSqh, (uint2*)gSql, NA4 };
    jobs.j[1] = { (const float4*)k,  (uint2*)gSkh, (uint2*)gSkl, NA4 };
    jobs.j[2] = { (const float4*)v,  (uint2*)gSvh, (uint2*)gSvl, NA4 };
    jobs.j[3] = { (const float4*)Wq, (uint2*)gW1h, (uint2*)gW1l, NW4 };
    jobs.j[4] = { (const float4*)Wk, (uint2*)gW2h, (uint2*)gW2l, NW4 };
    jobs.j[5] = { (const float4*)Wv, (uint2*)gW3h, (uint2*)gW3l, NW4 };
    jobs.j[6] = { (const float4*)Wo, (uint2*)gW4h, (uint2*)gW4l, NW4 };
    split_batch<<<dim3((NA4 + 1023) / 1024, 7), 256>>>(jobs);

    const float QSCALE = 0.125f * 1.4426950408889634f;
    GemmJobs gj;
    gj.j[0] = { gSqh, gSql, gW1h, gW1l, bq, gQh, gQl, QSCALE };
    gj.j[1] = { gSkh, gSkl, gW2h, gW2l, bk, gKh, gKl, 1.0f };
    gj.j[2] = { gSvh, gSvl, gW3h, gW3l, bv, gVh, gVl, 1.0f };
    dim3 gp3(DD / 64, NROW / 128, 3);
    gemm_hmma_qkv<<<gp3, 256, SM_GEMM_BYTES>>>(gj);

    dim3 gf(SS / 64, BB * HH);    // (32, 32) = 1024 CTAs
    fused_attn2<<<gf, 256, FA_SMEM>>>(gQh, gQl, gKh, gKl, gVh, gVl, attn_ptr, gAh, gAl);

    dim3 gp(DD / 64, NROW / 128);
    gemm_hmma_out<<<gp, 256, SM_GEMM_BYTES>>>(gAh, gAl, gW4h, gW4l, bo, out_ptr);
}

// round 17
// speedup vs baseline: 1.1699x; 1.0490x over previous
#include <cuda_runtime.h>
#include <cuda_bf16.h>
#include <cuda_fp16.h>
#include <math.h>
#include <stdint.h>

#define BB 2
#define SS 2048
#define DD 1024
#define HH 16
#define DH 64
#define NROW (BB*SS)
#define OUT_ELEMS ((size_t)BB*SS*DD)

// Scratch (device globals)
__device__ __nv_bfloat16 g_Ah[NROW*DD];        // attn O split (bf16, for out proj)
__device__ __nv_bfloat16 g_Al[NROW*DD];
__device__ __nv_bfloat16 g_Sqh[NROW*DD], g_Sql[NROW*DD];
__device__ __nv_bfloat16 g_Skh[NROW*DD], g_Skl[NROW*DD];
__device__ __nv_bfloat16 g_Svh[NROW*DD], g_Svl[NROW*DD];
__device__ __nv_bfloat16 g_W1h[DD*DD], g_W1l[DD*DD];
__device__ __nv_bfloat16 g_W2h[DD*DD], g_W2l[DD*DD];
__device__ __nv_bfloat16 g_W3h[DD*DD], g_W3l[DD*DD];
__device__ __nv_bfloat16 g_W4h[DD*DD], g_W4l[DD*DD];
// projected Q/K/V split-head: fp16 hi/lo
__device__ __half g_Qh[NROW*DD], g_Ql[NROW*DD];
__device__ __half g_Kh[NROW*DD], g_Kl[NROW*DD];
__device__ __half g_Vh[NROW*DD];

// ===========================================================================
// helpers
// ===========================================================================
__device__ __forceinline__ float fast_exp2(float x) {
    float r;
    asm("ex2.approx.f32 %0, %1;" : "=f"(r) : "f"(x));
    return r;
}
__device__ __forceinline__ uint32_t smem_u32(const void* p) {
    uint32_t a;
    asm("{ .reg .u64 t; cvta.to.shared.u64 t, %1; cvt.u32.u64 %0, t; }"
        : "=r"(a) : "l"(p));
    return a;
}
__device__ __forceinline__ uint32_t sw128(uint32_t off) {
    return off ^ ((off >> 3) & 0x70);
}
__device__ __forceinline__ void cp16(uint32_t dst, const void* src) {
    asm volatile("cp.async.cg.shared.global [%0], [%1], 16;"
                 :: "r"(dst), "l"(src));
}
__device__ __forceinline__ void cp_commit() {
    asm volatile("cp.async.commit_group;" ::: "memory");
}
__device__ __forceinline__ void ldsm_x4(uint32_t& r0, uint32_t& r1,
                                        uint32_t& r2, uint32_t& r3, uint32_t a) {
    asm volatile("ldmatrix.sync.aligned.m8n8.x4.shared.b16 {%0,%1,%2,%3}, [%4];"
                 : "=r"(r0), "=r"(r1), "=r"(r2), "=r"(r3) : "r"(a));
}
__device__ __forceinline__ void ldsm_x4t(uint32_t& r0, uint32_t& r1,
                                         uint32_t& r2, uint32_t& r3, uint32_t a) {
    asm volatile("ldmatrix.sync.aligned.m8n8.x4.trans.shared.b16 {%0,%1,%2,%3}, [%4];"
                 : "=r"(r0), "=r"(r1), "=r"(r2), "=r"(r3) : "r"(a));
}
// bf16 mma (projections)
__device__ __forceinline__ void mma16816(float* d, const uint32_t* a, const uint32_t* b) {
    asm volatile(
        "mma.sync.aligned.m16n8k16.row.col.f32.bf16.bf16.f32 "
        "{%0,%1,%2,%3}, {%4,%5,%6,%7}, {%8,%9}, {%0,%1,%2,%3};"
        : "+f"(d[0]), "+f"(d[1]), "+f"(d[2]), "+f"(d[3])
        : "r"(a[0]), "r"(a[1]), "r"(a[2]), "r"(a[3]), "r"(b[0]), "r"(b[1]));
}
// fp16 mma (attention)
__device__ __forceinline__ void mma16816h(float* d, const uint32_t* a, const uint32_t* b) {
    asm volatile(
        "mma.sync.aligned.m16n8k16.row.col.f32.f16.f16.f32 "
        "{%0,%1,%2,%3}, {%4,%5,%6,%7}, {%8,%9}, {%0,%1,%2,%3};"
        : "+f"(d[0]), "+f"(d[1]), "+f"(d[2]), "+f"(d[3])
        : "r"(a[0]), "r"(a[1]), "r"(a[2]), "r"(a[3]), "r"(b[0]), "r"(b[1]));
}
__device__ __forceinline__ uint32_t pack_bf16x2(float lo, float hi) {
    uint32_t r;
    asm("cvt.rn.bf16x2.f32 %0, %1, %2;" : "=r"(r) : "f"(hi), "f"(lo));
    return r;
}
__device__ __forceinline__ uint32_t pack_f16x2(float lo, float hi) {
    uint32_t r;
    asm("cvt.rn.f16x2.f32 %0, %1, %2;" : "=r"(r) : "f"(hi), "f"(lo));
    return r;
}
__device__ __forceinline__ float f16lo(uint32_t p) {
    return __half2float(__ushort_as_half((unsigned short)(p & 0xffffu)));
}
__device__ __forceinline__ float f16hi(uint32_t p) {
    return __half2float(__ushort_as_half((unsigned short)(p >> 16)));
}

// ===========================================================================
// batched fp32 -> bf16 hi/lo split (4 float4 per thread)
// ===========================================================================
struct SplitJob { const float4* in; uint2* hi; uint2* lo; int n4; };
struct SplitJobs { SplitJob j[7]; };

__device__ __forceinline__ void do_split(const float4* in, uint2* hi, uint2* lo, int i) {
    float4 v = in[i];
    float f[4] = {v.x, v.y, v.z, v.w};
    uint16_t h[4], l[4];
    #pragma unroll
    for (int j = 0; j < 4; j++) {
        __nv_bfloat16 hb = __float2bfloat16(f[j]);
        __nv_bfloat16 lb = __float2bfloat16(f[j] - __bfloat162float(hb));
        h[j] = __bfloat16_as_ushort(hb);
        l[j] = __bfloat16_as_ushort(lb);
    }
    hi[i] = make_uint2((uint32_t)h[0] | ((uint32_t)h[1] << 16),
                       (uint32_t)h[2] | ((uint32_t)h[3] << 16));
    lo[i] = make_uint2((uint32_t)l[0] | ((uint32_t)l[1] << 16),
                       (uint32_t)l[2] | ((uint32_t)l[3] << 16));
}

__global__ __launch_bounds__(256) void split_batch(SplitJobs jobs) {
    SplitJob jb = jobs.j[blockIdx.y];
    int base = blockIdx.x * 1024 + threadIdx.x;
    #pragma unroll
    for (int it = 0; it < 4; it++) {
        int i = base + it * 256;
        if (i < jb.n4) do_split(jb.in, jb.hi, jb.lo, i);
    }
}

// ===========================================================================
// HMMA bf16-split GEMM — CTA 128x64, 2 CTAs/SM (R15 proven)
// mode 0: fp32 store. mode 2: fp16 hi/lo split-head store (Q/K/V; lo=null skips).
// ===========================================================================
#define NTS 16
#define GSTAGE2 49152
#define SM_GEMM_BYTES 98304

struct GemmJob {
    const __nv_bfloat16 *ah, *al, *wh, *wl;
    const float* bias;
    __half *ch, *cl;
    float scale;
};
struct GemmJobs { GemmJob j[3]; };

__device__ __forceinline__ void gemm_core(
    const __nv_bfloat16* __restrict__ Agh, const __nv_bfloat16* __restrict__ Agl,
    const __nv_bfloat16* __restrict__ Wgh, const __nv_bfloat16* __restrict__ Wgl,
    const float* __restrict__ bias, float* __restrict__ C,
    __half* __restrict__ Ch, __half* __restrict__ Cl,
    float scale, int mode, char* smc)
{
    const uint32_t sb = smem_u32(smc);
    const int t = threadIdx.x;
    const int lane = t & 31;
    const int wid = t >> 5;
    const int wm = wid & 3;
    const int wn = wid >> 2;
    const int m0 = blockIdx.y * 128;
    const int n0 = blockIdx.x * 64;

    float acc[2][4][4] = {};

    auto prefetch = [&](int s) {
        const int ksl = s * 64;
        const uint32_t base = sb + (s & 1) * GSTAGE2;
        #pragma unroll
        for (int i = 0; i < 4; i++) {
            int idx = t + i * 256;
            int row = idx >> 3, ck = idx & 7;
            uint32_t so = sw128((uint32_t)(row * 128 + ck * 16));
            size_t g = (size_t)(m0 + row) * DD + ksl + ck * 8;
            cp16(base + so, Agh + g);
            cp16(base + 16384 + so, Agl + g);
        }
        #pragma unroll
        for (int i = 0; i < 2; i++) {
            int idx = t + i * 256;
            int kr = idx >> 3, cn = idx & 7;
            uint32_t so = sw128((uint32_t)(kr * 128 + cn * 16));
            size_t g = (size_t)(ksl + kr) * DD + n0 + cn * 8;
            cp16(base + 32768 + so, Wgh + g);
            cp16(base + 40960 + so, Wgl + g);
        }
        cp_commit();
    };

    prefetch(0);
    prefetch(1);

    for (int s = 0; s < NTS; s++) {
        if (s < NTS - 1) asm volatile("cp.async.wait_group 1;" ::: "memory");
        else             asm volatile("cp.async.wait_group 0;" ::: "memory");
        __syncthreads();

        const uint32_t aB  = sb + (s & 1) * GSTAGE2;
        const uint32_t alB = aB + 16384;
        const uint32_t bhB = aB + 32768;
        const uint32_t blB = aB + 40960;

        const int lg = lane >> 3, l7 = lane & 7;

        #pragma unroll
        for (int ks = 0; ks < 4; ks++) {
            const int kb = ks * 32;
            uint32_t bh[4][2], bl[4][2];
            #pragma unroll
            for (int jj = 0; jj < 2; jj++) {
                int ncol = wn * 32 + jj * 16;
                int krow = ks * 16 + (lg & 1) * 8 + l7;
                uint32_t off = sw128((uint32_t)(krow * 128 + ncol * 2 + (lg >> 1) * 16));
                uint32_t r0, r1, r2, r3;
                ldsm_x4t(r0, r1, r2, r3, bhB + off);
                bh[jj*2+0][0] = r0; bh[jj*2+0][1] = r1;
                bh[jj*2+1][0] = r2; bh[jj*2+1][1] = r3;
                ldsm_x4t(r0, r1, r2, r3, blB + off);
                bl[jj*2+0][0] = r0; bl[jj*2+0][1] = r1;
                bl[jj*2+1][0] = r2; bl[jj*2+1][1] = r3;
            }
            #pragma unroll
            for (int im = 0; im < 2; im++) {
                int arow = wm * 32 + im * 16 + (lg & 1) * 8 + l7;
                uint32_t off = sw128((uint32_t)(arow * 128 + kb + (lg >> 1) * 16));
                uint32_t ah[4], al[4];
                ldsm_x4(ah[0], ah[1], ah[2], ah[3], aB + off);
                ldsm_x4(al[0], al[1], al[2], al[3], alB + off);
                #pragma unroll
                for (int jn = 0; jn < 4; jn++) mma16816(acc[im][jn], ah, bh[jn]);
                #pragma unroll
                for (int jn = 0; jn < 4; jn++) mma16816(acc[im][jn], ah, bl[jn]);
                #pragma unroll
                for (int jn = 0; jn < 4; jn++) mma16816(acc[im][jn], al, bh[jn]);
            }
        }
        __syncthreads();
        if (s + 2 < NTS) prefetch(s + 2);
    }

    #pragma unroll
    for (int im = 0; im < 2; im++) {
        int r0 = m0 + wm * 32 + im * 16 + (lane >> 2);
        #pragma unroll
        for (int jn = 0; jn < 4; jn++) {
            int col = n0 + wn * 32 + jn * 8 + (lane & 3) * 2;
            float b0 = bias[col], b1 = bias[col + 1];
            float v00 = acc[im][jn][0] + b0, v01 = acc[im][jn][1] + b1;
            float v10 = acc[im][jn][2] + b0, v11 = acc[im][jn][3] + b1;
            if (mode == 0) {
                *(float2*)&C[(size_t)r0 * DD + col] = make_float2(v00, v01);
                *(float2*)&C[(size_t)(r0 + 8) * DD + col] = make_float2(v10, v11);
            } else {
                v00 *= scale; v01 *= scale; v10 *= scale; v11 *= scale;
                int h = col >> 6, dd = col & 63;
                int b_ = r0 >> 11, s0 = r0 & 2047;
                int b2 = (r0 + 8) >> 11, s1 = (r0 + 8) & 2047;
                size_t off0 = ((size_t)(b_ * HH + h) * SS + s0) * DH + dd;
                size_t off1 = ((size_t)(b2 * HH + h) * SS + s1) * DH + dd;
                uint32_t p0 = pack_f16x2(v00, v01);
                uint32_t p1 = pack_f16x2(v10, v11);
                *(uint32_t*)&Ch[off0] = p0;
                *(uint32_t*)&Ch[off1] = p1;
                if (Cl) {
                    uint32_t q0 = pack_f16x2(v00 - f16lo(p0), v01 - f16hi(p0));
                    uint32_t q1 = pack_f16x2(v10 - f16lo(p1), v11 - f16hi(p1));
                    *(uint32_t*)&Cl[off0] = q0;
                    *(uint32_t*)&Cl[off1] = q1;
                }
            }
        }
    }
}

__global__ __launch_bounds__(256, 2) void gemm_hmma_qkv(GemmJobs jobs) {
    extern __shared__ char smc[];
    GemmJob jb = jobs.j[blockIdx.z];
    gemm_core(jb.ah, jb.al, jb.wh, jb.wl, jb.bias, nullptr,
              jb.ch, jb.cl, jb.scale, 2, smc);
}

__global__ __launch_bounds__(256, 2) void gemm_hmma_out(
    const __nv_bfloat16* __restrict__ Agh, const __nv_bfloat16* __restrict__ Agl,
    const __nv_bfloat16* __restrict__ Wgh, const __nv_bfloat16* __restrict__ Wgl,
    const float* __restrict__ bias, float* __restrict__ C)
{
    extern __shared__ char smc[];
    gemm_core(Agh, Agl, Wgh, Wgl, bias, C, nullptr, nullptr, 1.0f, 0, smc);
}

// ===========================================================================
// Fused attention v9 (fp16 operands): CTA = 64 q-rows, warps 2M x 4C.
// Pass A: single-product QhKh (fp16 => Z err ~5e-5).
// Pass B: 3-product S (fp16); PV 2-product (Ph+Pl vs Vh; Vl never loaded).
// Stage (pass B): Kh 0 / Kl 16K / Vh 32K = 48KB.
// ===========================================================================
#define FA_Q 16384
#define FA_STAGE 49152
#define FA_ZRED (FA_Q + 2 * FA_STAGE)            // 114688
#define FA_SMEM (FA_ZRED + 1024)

__global__ __launch_bounds__(256, 1) void fused_attn2(
    const __half* __restrict__ Qh, const __half* __restrict__ Ql,
    const __half* __restrict__ Kh, const __half* __restrict__ Kl,
    const __half* __restrict__ Vh,
    float* __restrict__ attn,
    __nv_bfloat16* __restrict__ Oh, __nv_bfloat16* __restrict__ Ol)
{
    extern __shared__ char smc[];
    const uint32_t sb = smem_u32(smc);
    const int t = threadIdx.x, lane = t & 31, wid = t >> 5;
    const int m0 = blockIdx.x * 64, bh = blockIdx.y;
    const int wm = wid & 1, wc = wid >> 1;       // 2 M x 4 C
    const int mrow = wm * 32, ncol = wc * 32;
    const size_t gB = (size_t)bh * SS * DH;

    const uint32_t sQh = sb, sQl = sb + 8192;
    float* zred = (float*)(smc + FA_ZRED);       // [4][64]

    const int rBn = (lane & 7) + ((lane & 16) >> 1);
    const int cB  = ((lane & 8) << 1);
    const int rV  = (lane & 7) + (lane & 8);
    const int cV  = (lane >> 4) * 16;
    const int l15 = lane & 15, l16 = lane & 16;

    // Q loads
    #pragma unroll
    for (int i = 0; i < 2; i++) {
        int idx = t + i * 256;
        int row = idx >> 3, ck = idx & 7;
        uint32_t so = sw128((uint32_t)(row * 128 + ck * 16));
        size_t g = gB + (size_t)(m0 + row) * DH + ck * 8;
        cp16(sQh + so, Qh + g);
        cp16(sQl + so, Ql + g);
    }

    auto prefKh2 = [&](int it) {   // pass A: 256 K rows of Kh (32KB)
        uint32_t base = sb + FA_Q + (uint32_t)(it & 1) * 32768;
        #pragma unroll
        for (int i = 0; i < 8; i++) {
            int idx = t + i * 256;
            int row = idx >> 3, ck = idx & 7;
            uint32_t so = sw128((uint32_t)(row * 128 + ck * 16));
            cp16(base + so, Kh + gB + (size_t)(it * 256 + row) * DH + ck * 8);
        }
        cp_commit();
    };
    auto prefKV = [&](int kt) {    // pass B: 128 rows Kh/Kl/Vh (48KB)
        uint32_t base = sb + FA_Q + (uint32_t)(kt & 1) * FA_STAGE;
        #pragma unroll
        for (int i = 0; i < 4; i++) {
            int idx = t + i * 256;
            int row = idx >> 3, ck = idx & 7;
            uint32_t so = sw128((uint32_t)(row * 128 + ck * 16));
            size_t g = gB + (size_t)(kt * 128 + row) * DH + ck * 8;
            cp16(base + so, Kh + g);
            cp16(base + 16384 + so, Kl + g);
            cp16(base + 32768 + so, Vh + g);
        }
        cp_commit();
    };

    prefKh2(0);
    prefKh2(1);

    // ------------------- Pass A: Z sums -------------------
    float zs[2][2] = {};
    for (int it = 0; it < 8; it++) {
        if (it < 7) asm volatile("cp.async.wait_group 1;" ::: "memory");
        else        asm volatile("cp.async.wait_group 0;" ::: "memory");
        __syncthreads();
        uint32_t kb0 = sb + FA_Q + (uint32_t)(it & 1) * 32768;

        #pragma unroll
        for (int half = 0; half < 2; half++) {
            uint32_t kb = kb0 + (uint32_t)half * 16384;
            float acc[2][4][4] = {};
            #pragma unroll
            for (int kg = 0; kg < 4; kg++) {
                uint32_t kf[2][4];
                #pragma unroll
                for (int j = 0; j < 2; j++) {
                    uint32_t offB = sw128((uint32_t)((ncol + j * 16 + rBn) * 128 + kg * 32 + cB));
                    ldsm_x4(kf[j][0], kf[j][1], kf[j][2], kf[j][3], kb + offB);
                }
                #pragma unroll
                for (int im = 0; im < 2; im++) {
                    uint32_t offA = sw128((uint32_t)((mrow + im * 16 + l15) * 128 + kg * 32 + l16));
                    uint32_t ah[4];
                    ldsm_x4(ah[0], ah[1], ah[2], ah[3], sQh + offA);
                    #pragma unroll
                    for (int j = 0; j < 2; j++) {
                        mma16816h(acc[im][2*j],   ah, &kf[j][0]);
                        mma16816h(acc[im][2*j+1], ah, &kf[j][2]);
                    }
                }
            }
            #pragma unroll
            for (int im = 0; im < 2; im++)
                #pragma unroll
                for (int nt = 0; nt < 4; nt++) {
                    zs[im][0] += fast_exp2(acc[im][nt][0]) + fast_exp2(acc[im][nt][1]);
                    zs[im][1] += fast_exp2(acc[im][nt][2]) + fast_exp2(acc[im][nt][3]);
                }
        }
        __syncthreads();
        if (it + 2 < 8) prefKh2(it + 2);
    }

    #pragma unroll
    for (int im = 0; im < 2; im++) {
        zs[im][0] += __shfl_xor_sync(0xffffffffu, zs[im][0], 1);
        zs[im][0] += __shfl_xor_sync(0xffffffffu, zs[im][0], 2);
        zs[im][1] += __shfl_xor_sync(0xffffffffu, zs[im][1], 1);
        zs[im][1] += __shfl_xor_sync(0xffffffffu, zs[im][1], 2);
    }
    if ((lane & 3) == 0) {
        #pragma unroll
        for (int im = 0; im < 2; im++) {
            int r = mrow + im * 16 + (lane >> 2);
            zred[wc * 64 + r]     = zs[im][0];
            zred[wc * 64 + r + 8] = zs[im][1];
        }
    }
    __syncthreads();
    float invZ[2][2];
    #pragma unroll
    for (int im = 0; im < 2; im++) {
        int r = mrow + im * 16 + (lane >> 2);
        invZ[im][0] = 1.0f / (zred[r] + zred[64 + r] + zred[128 + r] + zred[192 + r]);
        invZ[im][1] = 1.0f / (zred[r + 8] + zred[64 + r + 8] + zred[128 + r + 8] + zred[192 + r + 8]);
    }
    __syncthreads();

    prefKV(0);
    prefKV(1);

    // ------------------- Pass B -------------------
    float o[2][8][4] = {};

    for (int kt = 0; kt < 16; kt++) {
        if (kt < 15) asm volatile("cp.async.wait_group 1;" ::: "memory");
        else         asm volatile("cp.async.wait_group 0;" ::: "memory");
        __syncthreads();
        uint32_t kb = sb + FA_Q + (uint32_t)(kt & 1) * FA_STAGE;

        float acc[2][4][4] = {};
        #pragma unroll
        for (int kg = 0; kg < 4; kg++) {
            uint32_t kfh[2][4], kfl[2][4];
            #pragma unroll
            for (int j = 0; j < 2; j++) {
                uint32_t offB = sw128((uint32_t)((ncol + j * 16 + rBn) * 128 + kg * 32 + cB));
                ldsm_x4(kfh[j][0], kfh[j][1], kfh[j][2], kfh[j][3], kb + offB);
                ldsm_x4(kfl[j][0], kfl[j][1], kfl[j][2], kfl[j][3], kb + 16384 + offB);
            }
            #pragma unroll
            for (int im = 0; im < 2; im++) {
                uint32_t offA = sw128((uint32_t)((mrow + im * 16 + l15) * 128 + kg * 32 + l16));
                uint32_t ah[4], al[4];
                ldsm_x4(ah[0], ah[1], ah[2], ah[3], sQh + offA);
                ldsm_x4(al[0], al[1], al[2], al[3], sQl + offA);
                #pragma unroll
                for (int j = 0; j < 2; j++) {
                    mma16816h(acc[im][2*j],   ah, &kfh[j][0]);
                    mma16816h(acc[im][2*j+1], ah, &kfh[j][2]);
                }
                #pragma unroll
                for (int j = 0; j < 2; j++) {
                    mma16816h(acc[im][2*j],   al, &kfh[j][0]);
                    mma16816h(acc[im][2*j+1], al, &kfh[j][2]);
                }
                #pragma unroll
                for (int j = 0; j < 2; j++) {
                    mma16816h(acc[im][2*j],   ah, &kfl[j][0]);
                    mma16816h(acc[im][2*j+1], ah, &kfl[j][2]);
                }
            }
        }

        // exp + attn store
        #pragma unroll
        for (int im = 0; im < 2; im++) {
            const size_t ar0 = (size_t)bh * SS + m0 + mrow + im * 16 + (lane >> 2);
            #pragma unroll
            for (int nt = 0; nt < 4; nt++) {
                float p0 = fast_exp2(acc[im][nt][0]) * invZ[im][0];
                float p1 = fast_exp2(acc[im][nt][1]) * invZ[im][0];
                float p2 = fast_exp2(acc[im][nt][2]) * invZ[im][1];
                float p3 = fast_exp2(acc[im][nt][3]) * invZ[im][1];
                acc[im][nt][0] = p0; acc[im][nt][1] = p1;
                acc[im][nt][2] = p2; acc[im][nt][3] = p3;
                int col = kt * 128 + ncol + nt * 8 + (lane & 3) * 2;
                *(float2*)&attn[ar0 * SS + col]       = make_float2(p0, p1);
                *(float2*)&attn[(ar0 + 8) * SS + col] = make_float2(p2, p3);
            }
        }

        // PV: 2-product fp16 (Ph + Pl vs Vh)
        #pragma unroll
        for (int kg = 0; kg < 2; kg++) {
            uint32_t vfh[4][4];
            #pragma unroll
            for (int j = 0; j < 4; j++) {
                uint32_t offV = sw128((uint32_t)((ncol + kg * 16 + rV) * 128 + j * 32 + cV));
                ldsm_x4t(vfh[j][0], vfh[j][1], vfh[j][2], vfh[j][3], kb + 32768 + offV);
            }
            #pragma unroll
            for (int im = 0; im < 2; im++) {
                uint32_t ph[4], pl[4];
                #pragma unroll
                for (int half = 0; half < 2; half++) {
                    float* a4 = acc[im][2 * kg + half];
                    uint32_t h0 = pack_f16x2(a4[0], a4[1]);
                    uint32_t h1 = pack_f16x2(a4[2], a4[3]);
                    ph[half*2 + 0] = h0;
                    ph[half*2 + 1] = h1;
                    pl[half*2 + 0] = pack_f16x2(a4[0] - f16lo(h0), a4[1] - f16hi(h0));
                    pl[half*2 + 1] = pack_f16x2(a4[2] - f16lo(h1), a4[3] - f16hi(h1));
                }
                #pragma unroll
                for (int j = 0; j < 4; j++) {
                    mma16816h(o[im][2*j],   ph, &vfh[j][0]);
                    mma16816h(o[im][2*j+1], ph, &vfh[j][2]);
                }
                #pragma unroll
                for (int j = 0; j < 4; j++) {
                    mma16816h(o[im][2*j],   pl, &vfh[j][0]);
                    mma16816h(o[im][2*j+1], pl, &vfh[j][2]);
                }
            }
        }
        __syncthreads();
        if (kt + 2 < 16) prefKV(kt + 2);
    }

    // ------------------- O reduction (4 col-warps) + epilogue -------------------
    __syncthreads();
    float* ored = (float*)(smc + FA_Q);   // [3][64][64] partials (48KB in stage area)
    if (wc > 0) {
        float* dst = ored + (size_t)(wc - 1) * 4096;
        #pragma unroll
        for (int im = 0; im < 2; im++)
            #pragma unroll
            for (int nt = 0; nt < 8; nt++) {
                int row = mrow + im * 16 + (lane >> 2);
                int col = nt * 8 + (lane & 3) * 2;
                *(float2*)&dst[row * 64 + col] = make_float2(o[im][nt][0], o[im][nt][1]);
                *(float2*)&dst[(row + 8) * 64 + col] = make_float2(o[im][nt][2], o[im][nt][3]);
            }
    }
    __syncthreads();
    if (wc == 0) {
        const int b = bh >> 4, h = bh & 15;
        #pragma unroll
        for (int im = 0; im < 2; im++)
            #pragma unroll
            for (int nt = 0; nt < 8; nt++) {
                int row = mrow + im * 16 + (lane >> 2);
                int col = nt * 8 + (lane & 3) * 2;
                float2 a0 = *(float2*)&ored[row * 64 + col];
                float2 b0 = *(float2*)&ored[4096 + row * 64 + col];
                float2 c0 = *(float2*)&ored[8192 + row * 64 + col];
                float2 a1 = *(float2*)&ored[(row + 8) * 64 + col];
                float2 b1 = *(float2*)&ored[4096 + (row + 8) * 64 + col];
                float2 c1 = *(float2*)&ored[8192 + (row + 8) * 64 + col];
                float v0 = o[im][nt][0] + a0.x + b0.x + c0.x;
                float v1 = o[im][nt][1] + a0.y + b0.y + c0.y;
                float v2 = o[im][nt][2] + a1.x + b1.x + c1.x;
                float v3 = o[im][nt][3] + a1.y + b1.y + c1.y;
                size_t gr = (size_t)(b * SS + m0 + row);
                int gc = h * 64 + col;
                size_t off0 = gr * DD + gc;
                size_t off1 = (gr + 8) * DD + gc;
                uint32_t p0 = pack_bf16x2(v0, v1);
                uint32_t p1 = pack_bf16x2(v2, v3);
                *(uint32_t*)&Oh[off0] = p0;
                *(uint32_t*)&Oh[off1] = p1;
                uint32_t q0 = pack_bf16x2(v0 - __uint_as_float(p0 << 16),
                                          v1 - __uint_as_float(p0 & 0xffff0000u));
                uint32_t q1 = pack_bf16x2(v2 - __uint_as_float(p1 << 16),
                                          v3 - __uint_as_float(p1 & 0xffff0000u));
                *(uint32_t*)&Ol[off0] = q0;
                *(uint32_t*)&Ol[off1] = q1;
            }
    }
}

// ===========================================================================
extern "C" void kernel_launch(void* const* d_in, const int* in_sizes, int n_in,
                              void* d_out, int out_size)
{
    const float* q  = (const float*)d_in[0];
    const float* k  = (const float*)d_in[1];
    const float* v  = (const float*)d_in[2];
    const float* Wq = (const float*)d_in[4];
    const float* bq = (const float*)d_in[5];
    const float* Wk = (const float*)d_in[6];
    const float* bk = (const float*)d_in[7];
    const float* Wv = (const float*)d_in[8];
    const float* bv = (const float*)d_in[9];
    const float* Wo = (const float*)d_in[10];
    const float* bo = (const float*)d_in[11];

    float* out_ptr  = (float*)d_out;
    float* attn_ptr = (float*)d_out + OUT_ELEMS;

    __nv_bfloat16 *gAh, *gAl;
    __nv_bfloat16 *gSqh, *gSql, *gSkh, *gSkl, *gSvh, *gSvl;
    __nv_bfloat16 *gW1h, *gW1l, *gW2h, *gW2l, *gW3h, *gW3l, *gW4h, *gW4l;
    __half *gQh, *gQl, *gKh, *gKl, *gVh;
    cudaGetSymbolAddress((void**)&gAh, g_Ah);
    cudaGetSymbolAddress((void**)&gAl, g_Al);
    cudaGetSymbolAddress((void**)&gSqh, g_Sqh); cudaGetSymbolAddress((void**)&gSql, g_Sql);
    cudaGetSymbolAddress((void**)&gSkh, g_Skh); cudaGetSymbolAddress((void**)&gSkl, g_Skl);
    cudaGetSymbolAddress((void**)&gSvh, g_Svh); cudaGetSymbolAddress((void**)&gSvl, g_Svl);
    cudaGetSymbolAddress((void**)&gW1h, g_W1h); cudaGetSymbolAddress((void**)&gW1l, g_W1l);
    cudaGetSymbolAddress((void**)&gW2h, g_W2h); cudaGetSymbolAddress((void**)&gW2l, g_W2l);
    cudaGetSymbolAddress((void**)&gW3h, g_W3h); cudaGetSymbolAddress((void**)&gW3l, g_W3l);
    cudaGetSymbolAddress((void**)&gW4h, g_W4h); cudaGetSymbolAddress((void**)&gW4l, g_W4l);
    cudaGetSymbolAddress((void**)&gQh, g_Qh); cudaGetSymbolAddress((void**)&gQl, g_Ql);
    cudaGetSymbolAddress((void**)&gKh, g_Kh); cudaGetSymbolAddress((void**)&gKl, g_Kl);
    cudaGetSymbolAddress((void**)&gVh, g_Vh);

    cudaFuncSetAttribute(gemm_hmma_qkv, cudaFuncAttributeMaxDynamicSharedMemorySize,
                         SM_GEMM_BYTES);
    cudaFuncSetAttribute(gemm_hmma_out, cudaFuncAttributeMaxDynamicSharedMemorySize,
                         SM_GEMM_BYTES);
    cudaFuncSetAttribute(fused_attn2, cudaFuncAttributeMaxDynamicSharedMemorySize,
                         FA_SMEM);

    const int NA4 = (int)(OUT_ELEMS / 4);
    const int NW4 = DD * DD / 4;

    SplitJobs jobs;
    jobs.j[0] = { (const float4*)q,  (uint2*)gSqh, (uint2*)gSql, NA4 };
    jobs.j[1] = { (const float4*)k,  (uint2*)gSkh, (uint2*)gSkl, NA4 };
    jobs.j[2] = { (const float4*)v,  (uint2*)gSvh, (uint2*)gSvl, NA4 };
    jobs.j[3] = { (const float4*)Wq, (uint2*)gW1h, (uint2*)gW1l, NW4 };
    jobs.j[4] = { (const float4*)Wk, (uint2*)gW2h, (uint2*)gW2l, NW4 };
    jobs.j[5] = { (const float4*)Wv, (uint2*)gW3h, (uint2*)gW3l, NW4 };
    jobs.j[6] = { (const float4*)Wo, (uint2*)gW4h, (uint2*)gW4l, NW4 };
    split_batch<<<dim3((NA4 + 1023) / 1024, 7), 256>>>(jobs);

    const float QSCALE = 0.125f * 1.4426950408889634f;
    GemmJobs gj;
    gj.j[0] = { gSqh, gSql, gW1h, gW1l, bq, gQh, gQl, QSCALE };
    gj.j[1] = { gSkh, gSkl, gW2h, gW2l, bk, gKh, gKl, 1.0f };
    gj.j[2] = { gSvh, gSvl, gW3h, gW3l, bv, gVh, nullptr, 1.0f };
    dim3 gp3(DD / 64, NROW / 128, 3);
    gemm_hmma_qkv<<<gp3, 256, SM_GEMM_BYTES>>>(gj);

    dim3 gf(SS / 64, BB * HH);    // (32, 32) = 1024 CTAs
    fused_attn2<<<gf, 256, FA_SMEM>>>(gQh, gQl, gKh, gKl, gVh, attn_ptr, gAh, gAl);

    dim3 gp(DD / 64, NROW / 128);
    gemm_hmma_out<<<gp, 256, SM_GEMM_BYTES>>>(gAh, gAl, gW4h, gW4l, bo, out_ptr);
}